// round 12
// baseline (speedup 1.0000x reference)
#include <cuda_runtime.h>
#include <cuda_bf16.h>
#include <cstdint>
#include <math.h>

#define HH 512
#define WW 512
#define HWPIX (HH*WW)

// ---------------- scratch (device globals) ----------------
__device__ __nv_bfloat16 g_ah[134217728];  // [8][H][W][64] fm hi
__device__ __nv_bfloat16 g_al[134217728];  // fm lo
__device__ __nv_bfloat16 g_bh[134217728];  // sup1 out, later relu(mpn1) hi
__device__ __nv_bfloat16 g_bl[134217728];  // lo
__device__ float g_fuse[2097152];          // [H][W][8]
__device__ float g_u32[8388608];           // [H][W][32]
__device__ __nv_bfloat16 g_w1t[73728];     // conv mpn1 [2][9][64][64]
__device__ __nv_bfloat16 g_w2t[73728];     // conv mpn2
__device__ __nv_bfloat16 g_wst[36864];     // conv sup2 [2][9][32][64] (ic padded)
__device__ __nv_bfloat16 g_w2m[32768];     // mlp W2 [2][128][128] (n,k)
__device__ __nv_bfloat16 g_w3m[32768];     // mlp W3 rows 0..127
__device__ __nv_bfloat16 g_w4m[8192];      // mlp W4 [2][32][128]

#define SWZ(off) ((off) ^ (((off) >> 3) & 0x70))

__device__ __forceinline__ uint32_t smem_u32(const void* p) {
    uint32_t a;
    asm("{ .reg .u64 t; cvta.to.shared.u64 t, %1; cvt.u32.u64 %0, t; }" : "=r"(a) : "l"(p));
    return a;
}
#define LDSM4(r0,r1,r2,r3,addr) \
    asm volatile("ldmatrix.sync.aligned.m8n8.x4.shared.b16 {%0,%1,%2,%3}, [%4];" \
        : "=r"(r0), "=r"(r1), "=r"(r2), "=r"(r3) : "r"(addr))
#define MMA16816(c,a0,a1,a2,a3,b0,b1) \
    asm volatile("mma.sync.aligned.m16n8k16.row.col.f32.bf16.bf16.f32 " \
        "{%0,%1,%2,%3},{%4,%5,%6,%7},{%8,%9},{%0,%1,%2,%3};" \
        : "+f"((c)[0]), "+f"((c)[1]), "+f"((c)[2]), "+f"((c)[3]) \
        : "r"(a0), "r"(a1), "r"(a2), "r"(a3), "r"(b0), "r"(b1))

__device__ __forceinline__ void split_store8(__nv_bfloat16* dh, __nv_bfloat16* dl, const float* v) {
    union { __nv_bfloat16 b[8]; uint4 u; } Hh, Ll;
#pragma unroll
    for (int j = 0; j < 8; j++) {
        __nv_bfloat16 hb = __float2bfloat16(v[j]);
        Hh.b[j] = hb;
        Ll.b[j] = __float2bfloat16(v[j] - __bfloat162float(hb));
    }
    *(uint4*)dh = Hh.u; *(uint4*)dl = Ll.u;
}

// ======================= MLP weight prep (transpose + split) =======================
__global__ void mlpprep_kernel(const float* __restrict__ W2, const float* __restrict__ W3,
                               const float* __restrict__ W4)
{
    int idx = blockIdx.x*256 + threadIdx.x;
    if (idx >= 36864) return;
    if (idx < 16384) {
        int n = idx >> 7, k = idx & 127;
        float w = W2[k*128 + n];
        __nv_bfloat16 hb = __float2bfloat16(w);
        g_w2m[idx] = hb;
        g_w2m[16384 + idx] = __float2bfloat16(w - __bfloat162float(hb));
    } else if (idx < 32768) {
        int j = idx - 16384;
        int n = j >> 7, k = j & 127;
        float w = W3[k*128 + n];
        __nv_bfloat16 hb = __float2bfloat16(w);
        g_w3m[j] = hb;
        g_w3m[16384 + j] = __float2bfloat16(w - __bfloat162float(hb));
    } else {
        int j = idx - 32768;
        int n = j >> 7, k = j & 127;
        float w = W4[k*32 + n];
        __nv_bfloat16 hb = __float2bfloat16(w);
        g_w4m[j] = hb;
        g_w4m[4096 + j] = __float2bfloat16(w - __bfloat162float(hb));
    }
}

// ======================= tensor MLP (256 threads, known-good) =======================
#define MW2H 0
#define MW2L 32768
#define MW3H 65536
#define MW3L 98304
#define MW4H 131072
#define MW4L 139264
#define MAH  147456
#define MAL  163840
#define MBH  180224
#define MBL  196608
#define MXS  212992
#define MW3D 215040
#define MB1  216576
#define MB2  217088
#define MB3  217600
#define MB4  218112
#define MW1  218240
#define MLP_TC_SMEM 219776

__device__ __forceinline__ void gemm64(uint32_t sb, int ahOff, int alOff, int whOff, int wlOff,
                                       int mw, int nbase, int npairs, int lane, float (*acc)[4])
{
    const int ar = mw*16 + (lane & 15);
    const uint32_t aRow = sb + ar*256;
    const int arx = ar & 7;
    const int brl = (lane & 7) + ((lane & 16) >> 1);
    const int cbk = (lane & 8) >> 3;
#pragma unroll
    for (int kc = 0; kc < 8; kc++) {
        int ca = kc*2 + (lane >> 4);
        uint32_t aoff = (uint32_t)((ca ^ arx) << 4);
        uint32_t ah0,ah1,ah2,ah3, al0,al1,al2,al3;
        LDSM4(ah0,ah1,ah2,ah3, aRow + ahOff + aoff);
        LDSM4(al0,al1,al2,al3, aRow + alOff + aoff);
#pragma unroll
        for (int ns = 0; ns < npairs; ns++) {
            int br = nbase + ns*16 + brl;
            int cb = kc*2 + cbk;
            uint32_t boff = br*256 + (uint32_t)(((cb ^ (br & 7))) << 4);
            uint32_t b0,b1,b2,b3;
            LDSM4(b0,b1,b2,b3, sb + whOff + boff);
            MMA16816(acc[ns*2],   ah0,ah1,ah2,ah3, b0,b1);
            MMA16816(acc[ns*2+1], ah0,ah1,ah2,ah3, b2,b3);
            MMA16816(acc[ns*2],   al0,al1,al2,al3, b0,b1);
            MMA16816(acc[ns*2+1], al0,al1,al2,al3, b2,b3);
            LDSM4(b0,b1,b2,b3, sb + wlOff + boff);
            MMA16816(acc[ns*2],   ah0,ah1,ah2,ah3, b0,b1);
            MMA16816(acc[ns*2+1], ah0,ah1,ah2,ah3, b2,b3);
        }
    }
}

__device__ __forceinline__ void act_store_pair(char* csm, int hOff, int lOff,
                                               int r, int n, float v0, float v1)
{
    uint32_t off = r*256 + (uint32_t)((((n>>3) ^ (r&7))) << 4) + (n&7)*2;
    union { __nv_bfloat16 b[2]; uint32_t u; } H, L;
    H.b[0] = __float2bfloat16(v0);
    H.b[1] = __float2bfloat16(v1);
    L.b[0] = __float2bfloat16(v0 - __bfloat162float(H.b[0]));
    L.b[1] = __float2bfloat16(v1 - __bfloat162float(H.b[1]));
    *(uint32_t*)(csm + hOff + off) = H.u;
    *(uint32_t*)(csm + lOff + off) = L.u;
}

__global__ void __launch_bounds__(256, 1) mlp_tc_kernel(
    const float* __restrict__ ray, const float* __restrict__ zbufs,
    const float* __restrict__ W1, const float* __restrict__ b1,
    const float* __restrict__ b2, const float* __restrict__ W3,
    const float* __restrict__ b3, const float* __restrict__ b4)
{
    extern __shared__ char csm[];
    const uint32_t sb = smem_u32(csm);
    const int tid = threadIdx.x, lane = tid & 31, wid = tid >> 5;
    const int mw = wid & 3, nh = wid >> 2;

    for (int i = tid; i < 4096; i += 256) {
        int term = i >> 11, j = i & 2047;
        int n = j >> 4, c = j & 15;
        uint32_t doff = n*256 + (uint32_t)((c ^ (n&7)) << 4);
        uint4 v2 = *(const uint4*)(g_w2m + term*16384 + n*128 + c*8);
        *(uint4*)(csm + MW2H + term*32768 + doff) = v2;
        uint4 v3 = *(const uint4*)(g_w3m + term*16384 + n*128 + c*8);
        *(uint4*)(csm + MW3H + term*32768 + doff) = v3;
        if (n < 32) {
            uint4 v4 = *(const uint4*)(g_w4m + term*4096 + n*128 + c*8);
            *(uint4*)(csm + MW4H + term*8192 + doff) = v4;
        }
    }
    for (int i = tid; i < 128; i += 256) {
        ((float*)(csm+MB1))[i] = b1[i];
        ((float*)(csm+MB2))[i] = b2[i];
        ((float*)(csm+MB3))[i] = b3[i];
    }
    if (tid < 32) ((float*)(csm+MB4))[tid] = b4[tid];
    for (int i = tid; i < 384; i += 256) {
        ((float*)(csm+MW1))[i]  = W1[i];
        ((float*)(csm+MW3D))[i] = W3[16384 + i];
    }
    __syncthreads();

    float* xs = (float*)(csm + MXS);
    const float* b2s = (const float*)(csm + MB2);
    const float* b3s = (const float*)(csm + MB3);
    const float* b4s = (const float*)(csm + MB4);

    for (int t = blockIdx.x; t < 32768; t += gridDim.x) {
        if (tid < 64) {
            int p  = t*64 + tid;
            int yx = p & (HWPIX - 1);
            int k  = p >> 18;
            const float* r = ray + (size_t)yx*7;
            float ox=r[0], oy=r[1], oz=r[2], dx=r[3], dy=r[4], dz=r[5], cs=r[6];
            float z = zbufs[(size_t)yx*8 + k];
            float s = z / cs;
            float* x = xs + tid*8;
            x[0]=ox+dx*s; x[1]=oy+dy*s; x[2]=oz+dz*s;
            x[3]=dx; x[4]=dy; x[5]=dz;
            x[6]=(z>0.f)?1.f:0.f; x[7]=0.f;
        }
        __syncthreads();

        {
            int p = tid & 63, ug = tid >> 6;
            const float* xp = xs + p*8;
            float x0=xp[0], x1=xp[1], x2=xp[2];
            const float* w1s = (const float*)(csm + MW1);
            const float* b1s = (const float*)(csm + MB1);
            float v[8];
#pragma unroll
            for (int q = 0; q < 4; q++) {
#pragma unroll
                for (int j = 0; j < 8; j++) {
                    int u = ug*32 + q*8 + j;
                    v[j] = fmaxf(b1s[u] + x0*w1s[u] + x1*w1s[128+u] + x2*w1s[256+u], 0.f);
                }
                int c = ug*4 + q;
                uint32_t off = p*256 + (uint32_t)((c ^ (p&7)) << 4);
                split_store8((__nv_bfloat16*)(csm + MAH + off),
                             (__nv_bfloat16*)(csm + MAL + off), v);
            }
        }
        __syncthreads();

        {
            float acc[8][4] = {};
            gemm64(sb, MAH, MAL, MW2H, MW2L, mw, nh*64, 4, lane, acc);
            int r0 = mw*16 + (lane>>2);
#pragma unroll
            for (int ns = 0; ns < 8; ns++) {
                int n = nh*64 + ns*8 + (lane&3)*2;
                float bb0 = b2s[n], bb1 = b2s[n+1];
                act_store_pair(csm, MBH, MBL, r0,   n, fmaxf(acc[ns][0]+bb0,0.f), fmaxf(acc[ns][1]+bb1,0.f));
                act_store_pair(csm, MBH, MBL, r0+8, n, fmaxf(acc[ns][2]+bb0,0.f), fmaxf(acc[ns][3]+bb1,0.f));
            }
        }
        __syncthreads();

        {
            float acc[8][4] = {};
            gemm64(sb, MBH, MBL, MW3H, MW3L, mw, nh*64, 4, lane, acc);
            int r0 = mw*16 + (lane>>2);
            const float* w3d = (const float*)(csm + MW3D);
            float dx0 = xs[r0*8+3],     dy0 = xs[r0*8+4],     dz0 = xs[r0*8+5];
            float dx1 = xs[(r0+8)*8+3], dy1 = xs[(r0+8)*8+4], dz1 = xs[(r0+8)*8+5];
#pragma unroll
            for (int ns = 0; ns < 8; ns++) {
                int n = nh*64 + ns*8 + (lane&3)*2;
                float w0a=w3d[n],   w0b=w3d[128+n],   w0c=w3d[256+n];
                float w1a=w3d[n+1], w1b=w3d[128+n+1], w1c=w3d[256+n+1];
                float v0 = fmaxf(acc[ns][0] + b3s[n]   + dx0*w0a + dy0*w0b + dz0*w0c, 0.f);
                float v1 = fmaxf(acc[ns][1] + b3s[n+1] + dx0*w1a + dy0*w1b + dz0*w1c, 0.f);
                float v2 = fmaxf(acc[ns][2] + b3s[n]   + dx1*w0a + dy1*w0b + dz1*w0c, 0.f);
                float v3 = fmaxf(acc[ns][3] + b3s[n+1] + dx1*w1a + dy1*w1b + dz1*w1c, 0.f);
                act_store_pair(csm, MAH, MAL, r0,   n, v0, v1);
                act_store_pair(csm, MAH, MAL, r0+8, n, v2, v3);
            }
        }
        __syncthreads();

        {
            float acc[2][4] = {};
            gemm64(sb, MAH, MAL, MW4H, MW4L, mw, nh*16, 1, lane, acc);
            int r0 = mw*16 + (lane>>2);
#pragma unroll
            for (int ns = 0; ns < 2; ns++) {
                int n = nh*16 + ns*8 + (lane&3)*2;
                float bb0 = b4s[n], bb1 = b4s[n+1];
#pragma unroll
                for (int hh = 0; hh < 2; hh++) {
                    int r = r0 + hh*8;
                    float mk = xs[r*8+6];
                    size_t P = (size_t)t*64 + r;
                    float v0 = (acc[ns][hh*2]   + bb0)*mk;
                    float v1 = (acc[ns][hh*2+1] + bb1)*mk;
                    union { __nv_bfloat16 b[2]; uint32_t u; } H, L;
                    H.b[0] = __float2bfloat16(v0);
                    H.b[1] = __float2bfloat16(v1);
                    L.b[0] = __float2bfloat16(v0 - __bfloat162float(H.b[0]));
                    L.b[1] = __float2bfloat16(v1 - __bfloat162float(H.b[1]));
                    *(uint32_t*)(g_ah + P*64 + n) = H.u;
                    *(uint32_t*)(g_al + P*64 + n) = L.u;
                }
            }
        }
        __syncthreads();
    }
}

// ======================= sup1: 3 -> 32 relu, split-store (ch 0..31 only) ========
__global__ void sup1_kernel(const float* __restrict__ colors,
                            const float* __restrict__ kw, const float* __restrict__ bw)
{
    __shared__ float wgt[864];
    int tx = threadIdx.x, ty = threadIdx.y, tid = ty*32 + tx;
    for (int i = tid; i < 864; i += 256) wgt[i] = kw[i];
    __syncthreads();
    int x = blockIdx.x*32 + tx, y = blockIdx.y*8 + ty, k = blockIdx.z;
    float4 acc[8];
#pragma unroll
    for (int j = 0; j < 8; j++) acc[j] = ((const float4*)bw)[j];
    for (int dy = 0; dy < 3; dy++)
    for (int dx = 0; dx < 3; dx++) {
        int iy = y + dy - 1, ix = x + dx - 1;
        if (iy < 0 || iy >= HH || ix < 0 || ix >= WW) continue;
        const float* cp = colors + ((size_t)iy*WW + ix)*24 + k*3;
        const float* wr = wgt + (dy*3 + dx)*96;
#pragma unroll
        for (int ic = 0; ic < 3; ic++) {
            float v = cp[ic];
            const float4* w4 = (const float4*)(wr + ic*32);
#pragma unroll
            for (int j = 0; j < 8; j++) {
                float4 w = w4[j];
                acc[j].x=fmaf(v,w.x,acc[j].x); acc[j].y=fmaf(v,w.y,acc[j].y);
                acc[j].z=fmaf(v,w.z,acc[j].z); acc[j].w=fmaf(v,w.w,acc[j].w);
            }
        }
    }
    size_t pix = (size_t)k*HWPIX + (size_t)y*WW + x;
    float v[32];
#pragma unroll
    for (int j = 0; j < 8; j++) {
        v[j*4]  =fmaxf(acc[j].x,0.f); v[j*4+1]=fmaxf(acc[j].y,0.f);
        v[j*4+2]=fmaxf(acc[j].z,0.f); v[j*4+3]=fmaxf(acc[j].w,0.f);
    }
#pragma unroll
    for (int q = 0; q < 4; q++)
        split_store8(g_bh + pix*64 + q*8, g_bl + pix*64 + q*8, v + q*8);
}

// ======================= conv weight preps =======================
__global__ void wprep_kernel(const float* __restrict__ kw, int which)
{
    int idx = blockIdx.x*256 + threadIdx.x;
    if (idx >= 73728) return;
    int t = idx / 36864, r = idx % 36864;
    int p = r >> 12, q = r & 4095;
    int oc = q >> 6, ic = q & 63;
    float w = kw[((size_t)p*64 + ic)*64 + oc];
    __nv_bfloat16 hb = __float2bfloat16(w);
    __nv_bfloat16 o = t ? __float2bfloat16(w - __bfloat162float(hb)) : hb;
    (which ? g_w2t : g_w1t)[idx] = o;
}

__global__ void wprep_sup2_kernel(const float* __restrict__ kw)
{
    int idx = blockIdx.x*256 + threadIdx.x;
    if (idx >= 36864) return;
    int t = idx / 18432, r = idx % 18432;
    int tap = r >> 11, q = r & 2047;
    int oc = q >> 6, ic = q & 63;
    float w = (ic < 32) ? kw[((size_t)tap*32 + ic)*32 + oc] : 0.f;
    __nv_bfloat16 hb = __float2bfloat16(w);
    g_wst[idx] = t ? __float2bfloat16(w - __bfloat162float(hb)) : hb;
}

// ===== mma.sync 64->64 3x3 conv, 3 output rows/block, 512 threads =====
#define PITCH 130
#define WOFF  83200                 // strip: 5 rows * 130 * 128
#define BOFF (WOFF + 147456)        // 230656
#define CONV_SMEM (BOFF + 256)      // 230912

template<int MODE>
__global__ void __launch_bounds__(512, 1) conv64_kernel(const float* __restrict__ bias)
{
    extern __shared__ char csm[];
    const uint32_t sb = smem_u32(csm);
    const int tid = threadIdx.x, wid = tid >> 5, lane = tid & 31;
    const int mw = wid & 7, nh = wid >> 3;
    const int y0 = blockIdx.x*3, k = blockIdx.y;
    const int g = lane >> 2, tg = lane & 3;

    {
        const __nv_bfloat16* ws = MODE ? g_w2t : g_w1t;
        for (int i = tid; i < 9216; i += 512) {
            uint4 v = *(const uint4*)(ws + i*8);
            *(uint4*)(csm + WOFF + SWZ(i*16)) = v;
        }
    }
    if (tid < 64) ((float*)(csm + BOFF))[tid] = bias[tid];

    const __nv_bfloat16* srcH = MODE ? g_bh : g_ah;
    const __nv_bfloat16* srcL = MODE ? g_bl : g_al;
    float* bs = (float*)(csm + BOFF);

    const uint32_t alane = (mw*16 + (lane & 15))*128 + (lane >> 4)*16;
    const uint32_t blane = ((lane & 7) + ((lane & 16) >> 1))*128 + (lane & 8)*2;

    for (int t = 0; t < 4; t++) {
        const int x0 = t*128;
        float acc[3][4][4];
#pragma unroll
        for (int r = 0; r < 3; r++)
#pragma unroll
            for (int s = 0; s < 4; s++)
#pragma unroll
                for (int j = 0; j < 4; j++) acc[r][s][j] = 0.f;

        for (int pass = 0; pass < 2; pass++) {
            const __nv_bfloat16* src = pass ? srcL : srcH;
            __syncthreads();
            for (int idx = tid; idx < 5200; idx += 512) {
                int r = idx >> 3, c = idx & 7;
                int dyw = r/130, sx = r - dyw*130;
                int iy = y0 - 1 + dyw, ix = x0 + sx - 1;
                uint4 v = make_uint4(0,0,0,0);
                if (iy >= 0 && iy < HH && (unsigned)ix < WW)
                    v = *(const uint4*)(src + ((size_t)k*HWPIX + (size_t)iy*WW + ix)*64 + c*8);
                *(uint4*)(csm + SWZ((dyw*PITCH + sx)*128 + c*16)) = v;
            }
            __syncthreads();

            const int nterm = pass ? 1 : 2;
            for (int tap = 0; tap < 9; tap++) {
                int dy = tap/3, dxo = tap - dy*3;
#pragma unroll
                for (int kc = 0; kc < 4; kc++) {
                    uint32_t a0[4], a1[4], a2[4];
                    LDSM4(a0[0],a0[1],a0[2],a0[3], sb + SWZ((dy*PITCH + dxo)*128 + alane + kc*32));
                    LDSM4(a1[0],a1[1],a1[2],a1[3], sb + SWZ(((dy+1)*PITCH + dxo)*128 + alane + kc*32));
                    LDSM4(a2[0],a2[1],a2[2],a2[3], sb + SWZ(((dy+2)*PITCH + dxo)*128 + alane + kc*32));
                    for (int tm = 0; tm < nterm; tm++) {
                        uint32_t wb = sb + WOFF + tm*73728;
#pragma unroll
                        for (int ns = 0; ns < 2; ns++) {
                            uint32_t b0,b1,b2,b3;
                            LDSM4(b0,b1,b2,b3, wb + SWZ(tap*8192 + (nh*2+ns)*2048 + kc*32 + blane));
                            MMA16816(acc[0][ns*2],   a0[0],a0[1],a0[2],a0[3], b0,b1);
                            MMA16816(acc[0][ns*2+1], a0[0],a0[1],a0[2],a0[3], b2,b3);
                            MMA16816(acc[1][ns*2],   a1[0],a1[1],a1[2],a1[3], b0,b1);
                            MMA16816(acc[1][ns*2+1], a1[0],a1[1],a1[2],a1[3], b2,b3);
                            MMA16816(acc[2][ns*2],   a2[0],a2[1],a2[2],a2[3], b0,b1);
                            MMA16816(acc[2][ns*2+1], a2[0],a2[1],a2[2],a2[3], b2,b3);
                        }
                    }
                }
            }
        }

        if (MODE == 0) {
#pragma unroll
            for (int r = 0; r < 3; r++) {
                if (y0 + r >= HH) continue;
#pragma unroll
                for (int s = 0; s < 4; s++) {
                    int oc = nh*32 + s*8 + tg*2;
                    float b0v = bs[oc], b1v = bs[oc+1];
#pragma unroll
                    for (int half = 0; half < 2; half++) {
                        int px = mw*16 + g + half*8;
                        int gx = x0 + px;
                        size_t pix = (size_t)k*HWPIX + (size_t)(y0+r)*WW + gx;
                        float v0 = fmaxf(acc[r][s][half*2]   + b0v, 0.f);
                        float v1 = fmaxf(acc[r][s][half*2+1] + b1v, 0.f);
                        union { __nv_bfloat16 b[2]; uint32_t u; } H, L;
                        H.b[0] = __float2bfloat16(v0);
                        H.b[1] = __float2bfloat16(v1);
                        L.b[0] = __float2bfloat16(v0 - __bfloat162float(H.b[0]));
                        L.b[1] = __float2bfloat16(v1 - __bfloat162float(H.b[1]));
                        *(uint32_t*)(g_bh + pix*64 + oc) = H.u;
                        *(uint32_t*)(g_bl + pix*64 + oc) = L.u;
                    }
                }
            }
        } else {
            float* fsm = (float*)csm;
            for (int r = 0; r < 3; r++) {
                __syncthreads();
                if (y0 + r >= HH) continue;
#pragma unroll
                for (int s = 0; s < 4; s++) {
                    int oc = nh*32 + s*8 + tg*2;
#pragma unroll
                    for (int half = 0; half < 2; half++) {
                        int px = mw*16 + g + half*8;
                        fsm[px*68 + oc]     = acc[r][s][half*2]   + bs[oc];
                        fsm[px*68 + oc + 1] = acc[r][s][half*2+1] + bs[oc+1];
                    }
                }
                __syncthreads();
                if (tid < 128) {
                    int gx = x0 + tid;
                    size_t pix = (size_t)k*HWPIX + (size_t)(y0+r)*WW + gx;
                    const uint4* ah4 = (const uint4*)(g_ah + pix*64);
                    const uint4* al4 = (const uint4*)(g_al + pix*64);
                    float alpha = 1.f, fuse = 0.f;
#pragma unroll
                    for (int q = 0; q < 8; q++) {
                        union { uint4 u; __nv_bfloat16 b[8]; } Ha, La;
                        Ha.u = ah4[q]; La.u = al4[q];
#pragma unroll
                        for (int j = 0; j < 8; j++) {
                            float a = fsm[tid*68 + q*8 + j];
                            float m = 1.f/(1.f + expf(-a));
                            float f = __bfloat162float(Ha.b[j]) + __bfloat162float(La.b[j]);
                            fuse += f*m*alpha;
                            alpha *= (1.f - m);
                        }
                    }
                    g_fuse[((size_t)(y0+r)*WW + gx)*8 + k] = fuse;
                }
            }
        }
    }
}

// ===== sup2 tensor conv, 3 rows/block, 512 threads: 32 -> 32, no relu =====
#define W2OFF 83200
#define B2OFF (W2OFF + 73728)
#define SUP2_SMEM (B2OFF + 128)

__global__ void __launch_bounds__(512, 1) sup2_tc_kernel(const float* __restrict__ bias)
{
    extern __shared__ char csm[];
    const uint32_t sb = smem_u32(csm);
    const int tid = threadIdx.x, wid = tid >> 5, lane = tid & 31;
    const int mw = wid & 7, nh = wid >> 3;
    const int y0 = blockIdx.x*3, k = blockIdx.y;
    const int g = lane >> 2, tg = lane & 3;

    for (int i = tid; i < 4608; i += 512) {
        uint4 v = *(const uint4*)(g_wst + i*8);
        *(uint4*)(csm + W2OFF + SWZ(i*16)) = v;
    }
    if (tid < 32) ((float*)(csm + B2OFF))[tid] = bias[tid];
    float* bs = (float*)(csm + B2OFF);

    const uint32_t alane = (mw*16 + (lane & 15))*128 + (lane >> 4)*16;
    const uint32_t blane = ((lane & 7) + ((lane & 16) >> 1))*128 + (lane & 8)*2;

    for (int t = 0; t < 4; t++) {
        const int x0 = t*128;
        float acc[3][2][4];
#pragma unroll
        for (int r = 0; r < 3; r++)
#pragma unroll
            for (int s = 0; s < 2; s++)
#pragma unroll
                for (int j = 0; j < 4; j++) acc[r][s][j] = 0.f;

        for (int pass = 0; pass < 2; pass++) {
            const __nv_bfloat16* src = pass ? g_bl : g_bh;
            __syncthreads();
            for (int idx = tid; idx < 2600; idx += 512) {
                int r = idx >> 2, c = idx & 3;
                int dyw = r/130, sx = r - dyw*130;
                int iy = y0 - 1 + dyw, ix = x0 + sx - 1;
                uint4 v = make_uint4(0,0,0,0);
                if (iy >= 0 && iy < HH && (unsigned)ix < WW)
                    v = *(const uint4*)(src + ((size_t)k*HWPIX + (size_t)iy*WW + ix)*64 + c*8);
                *(uint4*)(csm + SWZ((dyw*PITCH + sx)*128 + c*16)) = v;
            }
            __syncthreads();

            const int nterm = pass ? 1 : 2;
            for (int tap = 0; tap < 9; tap++) {
                int dy = tap/3, dxo = tap - dy*3;
#pragma unroll
                for (int kc = 0; kc < 2; kc++) {
                    uint32_t a0[4], a1[4], a2[4];
                    LDSM4(a0[0],a0[1],a0[2],a0[3], sb + SWZ((dy*PITCH + dxo)*128 + alane + kc*32));
                    LDSM4(a1[0],a1[1],a1[2],a1[3], sb + SWZ(((dy+1)*PITCH + dxo)*128 + alane + kc*32));
                    LDSM4(a2[0],a2[1],a2[2],a2[3], sb + SWZ(((dy+2)*PITCH + dxo)*128 + alane + kc*32));
                    for (int tm = 0; tm < nterm; tm++) {
                        uint32_t wb = sb + W2OFF + tm*36864;
                        uint32_t b0,b1,b2,b3;
                        LDSM4(b0,b1,b2,b3, wb + SWZ(tap*4096 + nh*2048 + kc*32 + blane));
                        MMA16816(acc[0][0], a0[0],a0[1],a0[2],a0[3], b0,b1);
                        MMA16816(acc[0][1], a0[0],a0[1],a0[2],a0[3], b2,b3);
                        MMA16816(acc[1][0], a1[0],a1[1],a1[2],a1[3], b0,b1);
                        MMA16816(acc[1][1], a1[0],a1[1],a1[2],a1[3], b2,b3);
                        MMA16816(acc[2][0], a2[0],a2[1],a2[2],a2[3], b0,b1);
                        MMA16816(acc[2][1], a2[0],a2[1],a2[2],a2[3], b2,b3);
                    }
                }
            }
        }

#pragma unroll
        for (int r = 0; r < 3; r++) {
            if (y0 + r >= HH) continue;
#pragma unroll
            for (int s = 0; s < 2; s++) {
                int oc = nh*16 + s*8 + tg*2;
                float b0v = bs[oc], b1v = bs[oc+1];
#pragma unroll
                for (int half = 0; half < 2; half++) {
                    int px = mw*16 + g + half*8;
                    int gx = x0 + px;
                    size_t pix = (size_t)k*HWPIX + (size_t)(y0+r)*WW + gx;
                    float v0 = acc[r][s][half*2]   + b0v;
                    float v1 = acc[r][s][half*2+1] + b1v;
                    union { __nv_bfloat16 b[2]; uint32_t u; } H, L;
                    H.b[0] = __float2bfloat16(v0);
                    H.b[1] = __float2bfloat16(v1);
                    L.b[0] = __float2bfloat16(v0 - __bfloat162float(H.b[0]));
                    L.b[1] = __float2bfloat16(v1 - __bfloat162float(H.b[1]));
                    *(uint32_t*)(g_ah + pix*64 + 32 + oc) = H.u;
                    *(uint32_t*)(g_al + pix*64 + 32 + oc) = L.u;
                }
            }
        }
    }
}

// ======================= un1: 8 -> 32 relu =======================
__global__ void un1_kernel(const float* __restrict__ kw, const float* __restrict__ bw)
{
    __shared__ float wgt[2304];
    int tx = threadIdx.x, ty = threadIdx.y, tid = ty*32 + tx;
    for (int i = tid; i < 2304; i += 256) wgt[i] = kw[i];
    __syncthreads();
    int x = blockIdx.x*32 + tx, y = blockIdx.y*8 + ty;
    float4 acc[8];
#pragma unroll
    for (int j = 0; j < 8; j++) acc[j] = ((const float4*)bw)[j];
    for (int dy = 0; dy < 3; dy++)
    for (int dx = 0; dx < 3; dx++) {
        int iy = y + dy - 1, ix = x + dx - 1;
        if (iy < 0 || iy >= HH || ix < 0 || ix >= WW) continue;
        const float* fp = g_fuse + ((size_t)iy*WW + ix)*8;
        float4 f0 = ((const float4*)fp)[0];
        float4 f1 = ((const float4*)fp)[1];
        float fv[8] = {f0.x,f0.y,f0.z,f0.w,f1.x,f1.y,f1.z,f1.w};
        const float* wr = wgt + (dy*3 + dx)*256;
#pragma unroll
        for (int ic = 0; ic < 8; ic++) {
            float v = fv[ic];
            const float4* w4 = (const float4*)(wr + ic*32);
#pragma unroll
            for (int j = 0; j < 8; j++) {
                float4 w = w4[j];
                acc[j].x=fmaf(v,w.x,acc[j].x); acc[j].y=fmaf(v,w.y,acc[j].y);
                acc[j].z=fmaf(v,w.z,acc[j].z); acc[j].w=fmaf(v,w.w,acc[j].w);
            }
        }
    }
    float* dst = g_u32 + ((size_t)y*WW + x)*32;
#pragma unroll
    for (int j = 0; j < 8; j++) {
        float4 o;
        o.x=fmaxf(acc[j].x,0.f); o.y=fmaxf(acc[j].y,0.f);
        o.z=fmaxf(acc[j].z,0.f); o.w=fmaxf(acc[j].w,0.f);
        ((float4*)dst)[j] = o;
    }
}

// ======================= un2: 32 -> 3 =======================
__global__ void un2_kernel(const float* __restrict__ kw, const float* __restrict__ bw,
                           float* __restrict__ out)
{
    __shared__ float wgt[864];
    int tx = threadIdx.x, ty = threadIdx.y, tid = ty*32 + tx;
    for (int i = tid; i < 864; i += 256) wgt[i] = kw[i];
    __syncthreads();
    int x = blockIdx.x*32 + tx, y = blockIdx.y*8 + ty;
    float a0 = bw[0], a1 = bw[1], a2 = bw[2];
    for (int dy = 0; dy < 3; dy++)
    for (int dx = 0; dx < 3; dx++) {
        int iy = y + dy - 1, ix = x + dx - 1;
        if (iy < 0 || iy >= HH || ix < 0 || ix >= WW) continue;
        const float* up = g_u32 + ((size_t)iy*WW + ix)*32;
        const float* wr = wgt + (dy*3 + dx)*96;
#pragma unroll
        for (int ic4 = 0; ic4 < 8; ic4++) {
            float4 v = ((const float4*)up)[ic4];
            float vv[4] = {v.x, v.y, v.z, v.w};
#pragma unroll
            for (int j = 0; j < 4; j++) {
                int ic = ic4*4 + j;
                a0 = fmaf(vv[j], wr[ic*3 + 0], a0);
                a1 = fmaf(vv[j], wr[ic*3 + 1], a1);
                a2 = fmaf(vv[j], wr[ic*3 + 2], a2);
            }
        }
    }
    float* dst = out + ((size_t)y*WW + x)*3;
    dst[0]=a0; dst[1]=a1; dst[2]=a2;
}

// ======================= launch =======================
extern "C" void kernel_launch(void* const* d_in, const int* in_sizes, int n_in,
                              void* d_out, int out_size)
{
    const float* colors = (const float*)d_in[0];
    const float* ray    = (const float*)d_in[1];
    const float* zbufs  = (const float*)d_in[2];
    const float* W1 = (const float*)d_in[3];  const float* b1 = (const float*)d_in[4];
    const float* W2 = (const float*)d_in[5];  const float* b2 = (const float*)d_in[6];
    const float* W3 = (const float*)d_in[7];  const float* b3 = (const float*)d_in[8];
    const float* W4 = (const float*)d_in[9];  const float* b4 = (const float*)d_in[10];
    const float* k_sup1 = (const float*)d_in[11]; const float* b_sup1 = (const float*)d_in[12];
    const float* k_sup2 = (const float*)d_in[13]; const float* b_sup2 = (const float*)d_in[14];
    const float* k_mpn1 = (const float*)d_in[15]; const float* b_mpn1 = (const float*)d_in[16];
    const float* k_mpn2 = (const float*)d_in[17]; const float* b_mpn2 = (const float*)d_in[18];
    const float* k_un1  = (const float*)d_in[19]; const float* b_un1  = (const float*)d_in[20];
    const float* k_un2  = (const float*)d_in[21]; const float* b_un2  = (const float*)d_in[22];
    float* out = (float*)d_out;

    static cudaStream_t sB = nullptr;
    static cudaEvent_t evRoot = nullptr, evB = nullptr;
    if (sB == nullptr) {
        cudaStreamCreateWithFlags(&sB, cudaStreamNonBlocking);
        cudaEventCreateWithFlags(&evRoot, cudaEventDisableTiming);
        cudaEventCreateWithFlags(&evB, cudaEventDisableTiming);
    }

    cudaFuncSetAttribute(mlp_tc_kernel, cudaFuncAttributeMaxDynamicSharedMemorySize, MLP_TC_SMEM);
    cudaFuncSetAttribute(sup2_tc_kernel, cudaFuncAttributeMaxDynamicSharedMemorySize, SUP2_SMEM);
    cudaFuncSetAttribute(conv64_kernel<0>, cudaFuncAttributeMaxDynamicSharedMemorySize, CONV_SMEM);
    cudaFuncSetAttribute(conv64_kernel<1>, cudaFuncAttributeMaxDynamicSharedMemorySize, CONV_SMEM);

    cudaEventRecord(evRoot, 0);
    cudaStreamWaitEvent(sB, evRoot, 0);

    mlpprep_kernel<<<144, 256>>>(W2, W3, W4);
    mlp_tc_kernel<<<148, 256, MLP_TC_SMEM>>>(ray, zbufs, W1, b1, b2, W3, b3, b4);

    wprep_kernel<<<288, 256, 0, sB>>>(k_mpn1, 0);
    wprep_kernel<<<288, 256, 0, sB>>>(k_mpn2, 1);
    wprep_sup2_kernel<<<144, 256, 0, sB>>>(k_sup2);
    sup1_kernel<<<dim3(16,64,8), dim3(32,8), 0, sB>>>(colors, k_sup1, b_sup1);
    sup2_tc_kernel<<<dim3(171,8), 512, SUP2_SMEM, sB>>>(b_sup2);

    cudaEventRecord(evB, sB);
    cudaStreamWaitEvent(0, evB, 0);

    conv64_kernel<0><<<dim3(171,8), 512, CONV_SMEM>>>(b_mpn1);
    conv64_kernel<1><<<dim3(171,8), 512, CONV_SMEM>>>(b_mpn2);
    un1_kernel<<<dim3(16,64), dim3(32,8)>>>(k_un1, b_un1);
    un2_kernel<<<dim3(16,64), dim3(32,8)>>>(k_un2, b_un2, out);
}

// round 13
// speedup vs baseline: 1.6372x; 1.6372x over previous
#include <cuda_runtime.h>
#include <cuda_bf16.h>
#include <cstdint>
#include <math.h>

#define HH 512
#define WW 512
#define HWPIX (HH*WW)

// ---------------- scratch (device globals) ----------------
__device__ __nv_bfloat16 g_ah[134217728];  // [8][H][W][64] fm hi
__device__ __nv_bfloat16 g_al[134217728];  // fm lo
__device__ __nv_bfloat16 g_bh[134217728];  // sup1 out, later relu(mpn1) hi
__device__ __nv_bfloat16 g_bl[134217728];  // lo
__device__ float g_fuse[2097152];          // [H][W][8]
__device__ float g_u32[8388608];           // [H][W][32]
__device__ __nv_bfloat16 g_w1t[73728];     // conv mpn1 [2][9][64][64]
__device__ __nv_bfloat16 g_w2t[73728];     // conv mpn2
__device__ __nv_bfloat16 g_wst[36864];     // conv sup2 [2][9][32][64] (ic padded)
__device__ __nv_bfloat16 g_w2m[32768];     // mlp W2 [2][128][128] (n,k)
__device__ __nv_bfloat16 g_w3m[32768];     // mlp W3 rows 0..127
__device__ __nv_bfloat16 g_w4m[8192];      // mlp W4 [2][32][128]

#define SWZ(off) ((off) ^ (((off) >> 3) & 0x70))

__device__ __forceinline__ uint32_t smem_u32(const void* p) {
    uint32_t a;
    asm("{ .reg .u64 t; cvta.to.shared.u64 t, %1; cvt.u32.u64 %0, t; }" : "=r"(a) : "l"(p));
    return a;
}
#define LDSM4(r0,r1,r2,r3,addr) \
    asm volatile("ldmatrix.sync.aligned.m8n8.x4.shared.b16 {%0,%1,%2,%3}, [%4];" \
        : "=r"(r0), "=r"(r1), "=r"(r2), "=r"(r3) : "r"(addr))
#define MMA16816(c,a0,a1,a2,a3,b0,b1) \
    asm volatile("mma.sync.aligned.m16n8k16.row.col.f32.bf16.bf16.f32 " \
        "{%0,%1,%2,%3},{%4,%5,%6,%7},{%8,%9},{%0,%1,%2,%3};" \
        : "+f"((c)[0]), "+f"((c)[1]), "+f"((c)[2]), "+f"((c)[3]) \
        : "r"(a0), "r"(a1), "r"(a2), "r"(a3), "r"(b0), "r"(b1))

__device__ __forceinline__ void split_store8(__nv_bfloat16* dh, __nv_bfloat16* dl, const float* v) {
    union { __nv_bfloat16 b[8]; uint4 u; } Hh, Ll;
#pragma unroll
    for (int j = 0; j < 8; j++) {
        __nv_bfloat16 hb = __float2bfloat16(v[j]);
        Hh.b[j] = hb;
        Ll.b[j] = __float2bfloat16(v[j] - __bfloat162float(hb));
    }
    *(uint4*)dh = Hh.u; *(uint4*)dl = Ll.u;
}

// ======================= MLP weight prep (transpose + split) =======================
__global__ void mlpprep_kernel(const float* __restrict__ W2, const float* __restrict__ W3,
                               const float* __restrict__ W4)
{
    int idx = blockIdx.x*256 + threadIdx.x;
    if (idx >= 36864) return;
    if (idx < 16384) {
        int n = idx >> 7, k = idx & 127;
        float w = W2[k*128 + n];
        __nv_bfloat16 hb = __float2bfloat16(w);
        g_w2m[idx] = hb;
        g_w2m[16384 + idx] = __float2bfloat16(w - __bfloat162float(hb));
    } else if (idx < 32768) {
        int j = idx - 16384;
        int n = j >> 7, k = j & 127;
        float w = W3[k*128 + n];
        __nv_bfloat16 hb = __float2bfloat16(w);
        g_w3m[j] = hb;
        g_w3m[16384 + j] = __float2bfloat16(w - __bfloat162float(hb));
    } else {
        int j = idx - 32768;
        int n = j >> 7, k = j & 127;
        float w = W4[k*32 + n];
        __nv_bfloat16 hb = __float2bfloat16(w);
        g_w4m[j] = hb;
        g_w4m[4096 + j] = __float2bfloat16(w - __bfloat162float(hb));
    }
}

// ======================= tensor MLP (256 threads) =======================
#define MW2H 0
#define MW2L 32768
#define MW3H 65536
#define MW3L 98304
#define MW4H 131072
#define MW4L 139264
#define MAH  147456
#define MAL  163840
#define MBH  180224
#define MBL  196608
#define MXS  212992
#define MW3D 215040
#define MB1  216576
#define MB2  217088
#define MB3  217600
#define MB4  218112
#define MW1  218240
#define MLP_TC_SMEM 219776

__device__ __forceinline__ void gemm64(uint32_t sb, int ahOff, int alOff, int whOff, int wlOff,
                                       int mw, int nbase, int npairs, int lane, float (*acc)[4])
{
    const int ar = mw*16 + (lane & 15);
    const uint32_t aRow = sb + ar*256;
    const int arx = ar & 7;
    const int brl = (lane & 7) + ((lane & 16) >> 1);
    const int cbk = (lane & 8) >> 3;
#pragma unroll
    for (int kc = 0; kc < 8; kc++) {
        int ca = kc*2 + (lane >> 4);
        uint32_t aoff = (uint32_t)((ca ^ arx) << 4);
        uint32_t ah0,ah1,ah2,ah3, al0,al1,al2,al3;
        LDSM4(ah0,ah1,ah2,ah3, aRow + ahOff + aoff);
        LDSM4(al0,al1,al2,al3, aRow + alOff + aoff);
#pragma unroll
        for (int ns = 0; ns < npairs; ns++) {
            int br = nbase + ns*16 + brl;
            int cb = kc*2 + cbk;
            uint32_t boff = br*256 + (uint32_t)(((cb ^ (br & 7))) << 4);
            uint32_t b0,b1,b2,b3;
            LDSM4(b0,b1,b2,b3, sb + whOff + boff);
            MMA16816(acc[ns*2],   ah0,ah1,ah2,ah3, b0,b1);
            MMA16816(acc[ns*2+1], ah0,ah1,ah2,ah3, b2,b3);
            MMA16816(acc[ns*2],   al0,al1,al2,al3, b0,b1);
            MMA16816(acc[ns*2+1], al0,al1,al2,al3, b2,b3);
            LDSM4(b0,b1,b2,b3, sb + wlOff + boff);
            MMA16816(acc[ns*2],   ah0,ah1,ah2,ah3, b0,b1);
            MMA16816(acc[ns*2+1], ah0,ah1,ah2,ah3, b2,b3);
        }
    }
}

__device__ __forceinline__ void act_store_pair(char* csm, int hOff, int lOff,
                                               int r, int n, float v0, float v1)
{
    uint32_t off = r*256 + (uint32_t)((((n>>3) ^ (r&7))) << 4) + (n&7)*2;
    union { __nv_bfloat16 b[2]; uint32_t u; } H, L;
    H.b[0] = __float2bfloat16(v0);
    H.b[1] = __float2bfloat16(v1);
    L.b[0] = __float2bfloat16(v0 - __bfloat162float(H.b[0]));
    L.b[1] = __float2bfloat16(v1 - __bfloat162float(H.b[1]));
    *(uint32_t*)(csm + hOff + off) = H.u;
    *(uint32_t*)(csm + lOff + off) = L.u;
}

__global__ void __launch_bounds__(256, 1) mlp_tc_kernel(
    const float* __restrict__ ray, const float* __restrict__ zbufs,
    const float* __restrict__ W1, const float* __restrict__ b1,
    const float* __restrict__ b2, const float* __restrict__ W3,
    const float* __restrict__ b3, const float* __restrict__ b4)
{
    extern __shared__ char csm[];
    const uint32_t sb = smem_u32(csm);
    const int tid = threadIdx.x, lane = tid & 31, wid = tid >> 5;
    const int mw = wid & 3, nh = wid >> 2;

    for (int i = tid; i < 4096; i += 256) {
        int term = i >> 11, j = i & 2047;
        int n = j >> 4, c = j & 15;
        uint32_t doff = n*256 + (uint32_t)((c ^ (n&7)) << 4);
        uint4 v2 = *(const uint4*)(g_w2m + term*16384 + n*128 + c*8);
        *(uint4*)(csm + MW2H + term*32768 + doff) = v2;
        uint4 v3 = *(const uint4*)(g_w3m + term*16384 + n*128 + c*8);
        *(uint4*)(csm + MW3H + term*32768 + doff) = v3;
        if (n < 32) {
            uint4 v4 = *(const uint4*)(g_w4m + term*4096 + n*128 + c*8);
            *(uint4*)(csm + MW4H + term*8192 + doff) = v4;
        }
    }
    for (int i = tid; i < 128; i += 256) {
        ((float*)(csm+MB1))[i] = b1[i];
        ((float*)(csm+MB2))[i] = b2[i];
        ((float*)(csm+MB3))[i] = b3[i];
    }
    if (tid < 32) ((float*)(csm+MB4))[tid] = b4[tid];
    for (int i = tid; i < 384; i += 256) {
        ((float*)(csm+MW1))[i]  = W1[i];
        ((float*)(csm+MW3D))[i] = W3[16384 + i];
    }
    __syncthreads();

    float* xs = (float*)(csm + MXS);
    const float* b2s = (const float*)(csm + MB2);
    const float* b3s = (const float*)(csm + MB3);
    const float* b4s = (const float*)(csm + MB4);

    for (int t = blockIdx.x; t < 32768; t += gridDim.x) {
        if (tid < 64) {
            int p  = t*64 + tid;
            int yx = p & (HWPIX - 1);
            int k  = p >> 18;
            const float* r = ray + (size_t)yx*7;
            float ox=r[0], oy=r[1], oz=r[2], dx=r[3], dy=r[4], dz=r[5], cs=r[6];
            float z = zbufs[(size_t)yx*8 + k];
            float s = z / cs;
            float* x = xs + tid*8;
            x[0]=ox+dx*s; x[1]=oy+dy*s; x[2]=oz+dz*s;
            x[3]=dx; x[4]=dy; x[5]=dz;
            x[6]=(z>0.f)?1.f:0.f; x[7]=0.f;
        }
        __syncthreads();

        {
            int p = tid & 63, ug = tid >> 6;
            const float* xp = xs + p*8;
            float x0=xp[0], x1=xp[1], x2=xp[2];
            const float* w1s = (const float*)(csm + MW1);
            const float* b1s = (const float*)(csm + MB1);
            float v[8];
#pragma unroll
            for (int q = 0; q < 4; q++) {
#pragma unroll
                for (int j = 0; j < 8; j++) {
                    int u = ug*32 + q*8 + j;
                    v[j] = fmaxf(b1s[u] + x0*w1s[u] + x1*w1s[128+u] + x2*w1s[256+u], 0.f);
                }
                int c = ug*4 + q;
                uint32_t off = p*256 + (uint32_t)((c ^ (p&7)) << 4);
                split_store8((__nv_bfloat16*)(csm + MAH + off),
                             (__nv_bfloat16*)(csm + MAL + off), v);
            }
        }
        __syncthreads();

        {
            float acc[8][4] = {};
            gemm64(sb, MAH, MAL, MW2H, MW2L, mw, nh*64, 4, lane, acc);
            int r0 = mw*16 + (lane>>2);
#pragma unroll
            for (int ns = 0; ns < 8; ns++) {
                int n = nh*64 + ns*8 + (lane&3)*2;
                float bb0 = b2s[n], bb1 = b2s[n+1];
                act_store_pair(csm, MBH, MBL, r0,   n, fmaxf(acc[ns][0]+bb0,0.f), fmaxf(acc[ns][1]+bb1,0.f));
                act_store_pair(csm, MBH, MBL, r0+8, n, fmaxf(acc[ns][2]+bb0,0.f), fmaxf(acc[ns][3]+bb1,0.f));
            }
        }
        __syncthreads();

        {
            float acc[8][4] = {};
            gemm64(sb, MBH, MBL, MW3H, MW3L, mw, nh*64, 4, lane, acc);
            int r0 = mw*16 + (lane>>2);
            const float* w3d = (const float*)(csm + MW3D);
            float dx0 = xs[r0*8+3],     dy0 = xs[r0*8+4],     dz0 = xs[r0*8+5];
            float dx1 = xs[(r0+8)*8+3], dy1 = xs[(r0+8)*8+4], dz1 = xs[(r0+8)*8+5];
#pragma unroll
            for (int ns = 0; ns < 8; ns++) {
                int n = nh*64 + ns*8 + (lane&3)*2;
                float w0a=w3d[n],   w0b=w3d[128+n],   w0c=w3d[256+n];
                float w1a=w3d[n+1], w1b=w3d[128+n+1], w1c=w3d[256+n+1];
                float v0 = fmaxf(acc[ns][0] + b3s[n]   + dx0*w0a + dy0*w0b + dz0*w0c, 0.f);
                float v1 = fmaxf(acc[ns][1] + b3s[n+1] + dx0*w1a + dy0*w1b + dz0*w1c, 0.f);
                float v2 = fmaxf(acc[ns][2] + b3s[n]   + dx1*w0a + dy1*w0b + dz1*w0c, 0.f);
                float v3 = fmaxf(acc[ns][3] + b3s[n+1] + dx1*w1a + dy1*w1b + dz1*w1c, 0.f);
                act_store_pair(csm, MAH, MAL, r0,   n, v0, v1);
                act_store_pair(csm, MAH, MAL, r0+8, n, v2, v3);
            }
        }
        __syncthreads();

        {
            float acc[2][4] = {};
            gemm64(sb, MAH, MAL, MW4H, MW4L, mw, nh*16, 1, lane, acc);
            int r0 = mw*16 + (lane>>2);
#pragma unroll
            for (int ns = 0; ns < 2; ns++) {
                int n = nh*16 + ns*8 + (lane&3)*2;
                float bb0 = b4s[n], bb1 = b4s[n+1];
#pragma unroll
                for (int hh = 0; hh < 2; hh++) {
                    int r = r0 + hh*8;
                    float mk = xs[r*8+6];
                    size_t P = (size_t)t*64 + r;
                    float v0 = (acc[ns][hh*2]   + bb0)*mk;
                    float v1 = (acc[ns][hh*2+1] + bb1)*mk;
                    union { __nv_bfloat16 b[2]; uint32_t u; } H, L;
                    H.b[0] = __float2bfloat16(v0);
                    H.b[1] = __float2bfloat16(v1);
                    L.b[0] = __float2bfloat16(v0 - __bfloat162float(H.b[0]));
                    L.b[1] = __float2bfloat16(v1 - __bfloat162float(H.b[1]));
                    *(uint32_t*)(g_ah + P*64 + n) = H.u;
                    *(uint32_t*)(g_al + P*64 + n) = L.u;
                }
            }
        }
        __syncthreads();
    }
}

// ======================= sup1: 3 -> 32 relu, split-store (ch 0..31 only) ========
__global__ void sup1_kernel(const float* __restrict__ colors,
                            const float* __restrict__ kw, const float* __restrict__ bw)
{
    __shared__ float wgt[864];
    int tx = threadIdx.x, ty = threadIdx.y, tid = ty*32 + tx;
    for (int i = tid; i < 864; i += 256) wgt[i] = kw[i];
    __syncthreads();
    int x = blockIdx.x*32 + tx, y = blockIdx.y*8 + ty, k = blockIdx.z;
    float4 acc[8];
#pragma unroll
    for (int j = 0; j < 8; j++) acc[j] = ((const float4*)bw)[j];
    for (int dy = 0; dy < 3; dy++)
    for (int dx = 0; dx < 3; dx++) {
        int iy = y + dy - 1, ix = x + dx - 1;
        if (iy < 0 || iy >= HH || ix < 0 || ix >= WW) continue;
        const float* cp = colors + ((size_t)iy*WW + ix)*24 + k*3;
        const float* wr = wgt + (dy*3 + dx)*96;
#pragma unroll
        for (int ic = 0; ic < 3; ic++) {
            float v = cp[ic];
            const float4* w4 = (const float4*)(wr + ic*32);
#pragma unroll
            for (int j = 0; j < 8; j++) {
                float4 w = w4[j];
                acc[j].x=fmaf(v,w.x,acc[j].x); acc[j].y=fmaf(v,w.y,acc[j].y);
                acc[j].z=fmaf(v,w.z,acc[j].z); acc[j].w=fmaf(v,w.w,acc[j].w);
            }
        }
    }
    size_t pix = (size_t)k*HWPIX + (size_t)y*WW + x;
    float v[32];
#pragma unroll
    for (int j = 0; j < 8; j++) {
        v[j*4]  =fmaxf(acc[j].x,0.f); v[j*4+1]=fmaxf(acc[j].y,0.f);
        v[j*4+2]=fmaxf(acc[j].z,0.f); v[j*4+3]=fmaxf(acc[j].w,0.f);
    }
#pragma unroll
    for (int q = 0; q < 4; q++)
        split_store8(g_bh + pix*64 + q*8, g_bl + pix*64 + q*8, v + q*8);
}

// ======================= conv weight preps =======================
__global__ void wprep_kernel(const float* __restrict__ kw, int which)
{
    int idx = blockIdx.x*256 + threadIdx.x;
    if (idx >= 73728) return;
    int t = idx / 36864, r = idx % 36864;
    int p = r >> 12, q = r & 4095;
    int oc = q >> 6, ic = q & 63;
    float w = kw[((size_t)p*64 + ic)*64 + oc];
    __nv_bfloat16 hb = __float2bfloat16(w);
    __nv_bfloat16 o = t ? __float2bfloat16(w - __bfloat162float(hb)) : hb;
    (which ? g_w2t : g_w1t)[idx] = o;
}

__global__ void wprep_sup2_kernel(const float* __restrict__ kw)
{
    int idx = blockIdx.x*256 + threadIdx.x;
    if (idx >= 36864) return;
    int t = idx / 18432, r = idx % 18432;
    int tap = r >> 11, q = r & 2047;
    int oc = q >> 6, ic = q & 63;
    float w = (ic < 32) ? kw[((size_t)tap*32 + ic)*32 + oc] : 0.f;
    __nv_bfloat16 hb = __float2bfloat16(w);
    g_wst[idx] = t ? __float2bfloat16(w - __bfloat162float(hb)) : hb;
}

// ===== mma.sync 64->64 3x3 conv, 2 output rows/block, 512 threads =====
#define PITCH 136
#define WOFF  69632                 // strip: 4 rows * 136 * 128 = 69632
#define BOFF (WOFF + 147456)        // 217088
#define CONV_SMEM (BOFF + 256)      // 217344

template<int MODE>
__global__ void __launch_bounds__(512, 1) conv64_kernel(const float* __restrict__ bias)
{
    extern __shared__ char csm[];
    const uint32_t sb = smem_u32(csm);
    const int tid = threadIdx.x, wid = tid >> 5, lane = tid & 31;
    const int mw = wid & 7, nh = wid >> 3;
    const int y0 = blockIdx.x*2, k = blockIdx.y;
    const int g = lane >> 2, tg = lane & 3;

    {
        const __nv_bfloat16* ws = MODE ? g_w2t : g_w1t;
        for (int i = tid; i < 9216; i += 512) {
            uint4 v = *(const uint4*)(ws + i*8);
            *(uint4*)(csm + WOFF + SWZ(i*16)) = v;
        }
    }
    if (tid < 64) ((float*)(csm + BOFF))[tid] = bias[tid];

    const __nv_bfloat16* srcH = MODE ? g_bh : g_ah;
    const __nv_bfloat16* srcL = MODE ? g_bl : g_al;
    float* bs = (float*)(csm + BOFF);

    const uint32_t alane = (mw*16 + (lane & 15))*128 + (lane >> 4)*16;
    const uint32_t blane = ((lane & 7) + ((lane & 16) >> 1))*128 + (lane & 8)*2;

    for (int t = 0; t < 4; t++) {
        const int x0 = t*128;
        float acc[2][4][4];
#pragma unroll
        for (int r = 0; r < 2; r++)
#pragma unroll
            for (int s = 0; s < 4; s++)
#pragma unroll
                for (int j = 0; j < 4; j++) acc[r][s][j] = 0.f;

        for (int pass = 0; pass < 2; pass++) {
            const __nv_bfloat16* src = pass ? srcL : srcH;
            __syncthreads();
            for (int idx = tid; idx < 4160; idx += 512) {
                int r = idx >> 3, c = idx & 7;
                int dyw = r/130, sx = r - dyw*130;
                int iy = y0 - 1 + dyw, ix = x0 + sx - 1;
                uint4 v = make_uint4(0,0,0,0);
                if (iy >= 0 && iy < HH && (unsigned)ix < WW)
                    v = *(const uint4*)(src + ((size_t)k*HWPIX + (size_t)iy*WW + ix)*64 + c*8);
                *(uint4*)(csm + SWZ((dyw*PITCH + sx)*128 + c*16)) = v;
            }
            __syncthreads();

            const int nterm = pass ? 1 : 2;
            for (int tap = 0; tap < 9; tap++) {
                int dy = tap/3, dxo = tap - dy*3;
#pragma unroll
                for (int kc = 0; kc < 4; kc++) {
                    uint32_t a00,a01,a02,a03, a10,a11,a12,a13;
                    LDSM4(a00,a01,a02,a03, sb + SWZ((dy*PITCH + dxo)*128 + alane + kc*32));
                    LDSM4(a10,a11,a12,a13, sb + SWZ(((dy+1)*PITCH + dxo)*128 + alane + kc*32));
                    for (int tm = 0; tm < nterm; tm++) {
                        uint32_t wb = sb + WOFF + tm*73728;
#pragma unroll
                        for (int ns = 0; ns < 2; ns++) {
                            uint32_t b0,b1,b2,b3;
                            LDSM4(b0,b1,b2,b3, wb + SWZ(tap*8192 + (nh*2+ns)*2048 + kc*32 + blane));
                            MMA16816(acc[0][ns*2],   a00,a01,a02,a03, b0,b1);
                            MMA16816(acc[0][ns*2+1], a00,a01,a02,a03, b2,b3);
                            MMA16816(acc[1][ns*2],   a10,a11,a12,a13, b0,b1);
                            MMA16816(acc[1][ns*2+1], a10,a11,a12,a13, b2,b3);
                        }
                    }
                }
            }
        }

        if (MODE == 0) {
#pragma unroll
            for (int r = 0; r < 2; r++)
#pragma unroll
            for (int s = 0; s < 4; s++) {
                int oc = nh*32 + s*8 + tg*2;
                float b0v = bs[oc], b1v = bs[oc+1];
#pragma unroll
                for (int half = 0; half < 2; half++) {
                    int px = mw*16 + g + half*8;
                    int gx = x0 + px;
                    size_t pix = (size_t)k*HWPIX + (size_t)(y0+r)*WW + gx;
                    float v0 = fmaxf(acc[r][s][half*2]   + b0v, 0.f);
                    float v1 = fmaxf(acc[r][s][half*2+1] + b1v, 0.f);
                    union { __nv_bfloat16 b[2]; uint32_t u; } H, L;
                    H.b[0] = __float2bfloat16(v0);
                    H.b[1] = __float2bfloat16(v1);
                    L.b[0] = __float2bfloat16(v0 - __bfloat162float(H.b[0]));
                    L.b[1] = __float2bfloat16(v1 - __bfloat162float(H.b[1]));
                    *(uint32_t*)(g_bh + pix*64 + oc) = H.u;
                    *(uint32_t*)(g_bl + pix*64 + oc) = L.u;
                }
            }
        } else {
            float* fsm = (float*)csm;
            for (int r = 0; r < 2; r++) {
                __syncthreads();
#pragma unroll
                for (int s = 0; s < 4; s++) {
                    int oc = nh*32 + s*8 + tg*2;
#pragma unroll
                    for (int half = 0; half < 2; half++) {
                        int px = mw*16 + g + half*8;
                        fsm[px*68 + oc]     = acc[r][s][half*2]   + bs[oc];
                        fsm[px*68 + oc + 1] = acc[r][s][half*2+1] + bs[oc+1];
                    }
                }
                __syncthreads();
                if (tid < 128) {
                    int gx = x0 + tid;
                    size_t pix = (size_t)k*HWPIX + (size_t)(y0+r)*WW + gx;
                    const uint4* ah4 = (const uint4*)(g_ah + pix*64);
                    const uint4* al4 = (const uint4*)(g_al + pix*64);
                    float alpha = 1.f, fuse = 0.f;
#pragma unroll
                    for (int q = 0; q < 8; q++) {
                        union { uint4 u; __nv_bfloat16 b[8]; } Ha, La;
                        Ha.u = ah4[q]; La.u = al4[q];
#pragma unroll
                        for (int j = 0; j < 8; j++) {
                            float a = fsm[tid*68 + q*8 + j];
                            float m = 1.f/(1.f + expf(-a));
                            float f = __bfloat162float(Ha.b[j]) + __bfloat162float(La.b[j]);
                            fuse += f*m*alpha;
                            alpha *= (1.f - m);
                        }
                    }
                    g_fuse[((size_t)(y0+r)*WW + gx)*8 + k] = fuse;
                }
            }
        }
    }
}

// ===== sup2 tensor conv, 2 rows/block, 512 threads: 32 -> 32, no relu =====
#define W2OFF 69632
#define B2OFF (W2OFF + 73728)
#define SUP2_SMEM (B2OFF + 128)

__global__ void __launch_bounds__(512, 1) sup2_tc_kernel(const float* __restrict__ bias)
{
    extern __shared__ char csm[];
    const uint32_t sb = smem_u32(csm);
    const int tid = threadIdx.x, wid = tid >> 5, lane = tid & 31;
    const int mw = wid & 7, nh = wid >> 3;
    const int y0 = blockIdx.x*2, k = blockIdx.y;
    const int g = lane >> 2, tg = lane & 3;

    for (int i = tid; i < 4608; i += 512) {
        uint4 v = *(const uint4*)(g_wst + i*8);
        *(uint4*)(csm + W2OFF + SWZ(i*16)) = v;
    }
    if (tid < 32) ((float*)(csm + B2OFF))[tid] = bias[tid];
    float* bs = (float*)(csm + B2OFF);

    const uint32_t alane = (mw*16 + (lane & 15))*128 + (lane >> 4)*16;
    const uint32_t blane = ((lane & 7) + ((lane & 16) >> 1))*128 + (lane & 8)*2;

    for (int t = 0; t < 4; t++) {
        const int x0 = t*128;
        float acc[2][2][4];
#pragma unroll
        for (int r = 0; r < 2; r++)
#pragma unroll
            for (int s = 0; s < 2; s++)
#pragma unroll
                for (int j = 0; j < 4; j++) acc[r][s][j] = 0.f;

        for (int pass = 0; pass < 2; pass++) {
            const __nv_bfloat16* src = pass ? g_bl : g_bh;
            __syncthreads();
            for (int idx = tid; idx < 2080; idx += 512) {
                int r = idx >> 2, c = idx & 3;
                int dyw = r/130, sx = r - dyw*130;
                int iy = y0 - 1 + dyw, ix = x0 + sx - 1;
                uint4 v = make_uint4(0,0,0,0);
                if (iy >= 0 && iy < HH && (unsigned)ix < WW)
                    v = *(const uint4*)(src + ((size_t)k*HWPIX + (size_t)iy*WW + ix)*64 + c*8);
                *(uint4*)(csm + SWZ((dyw*PITCH + sx)*128 + c*16)) = v;
            }
            __syncthreads();

            const int nterm = pass ? 1 : 2;
            for (int tap = 0; tap < 9; tap++) {
                int dy = tap/3, dxo = tap - dy*3;
#pragma unroll
                for (int kc = 0; kc < 2; kc++) {
                    uint32_t a00,a01,a02,a03, a10,a11,a12,a13;
                    LDSM4(a00,a01,a02,a03, sb + SWZ((dy*PITCH + dxo)*128 + alane + kc*32));
                    LDSM4(a10,a11,a12,a13, sb + SWZ(((dy+1)*PITCH + dxo)*128 + alane + kc*32));
                    for (int tm = 0; tm < nterm; tm++) {
                        uint32_t wb = sb + W2OFF + tm*36864;
                        uint32_t b0,b1,b2,b3;
                        LDSM4(b0,b1,b2,b3, wb + SWZ(tap*4096 + nh*2048 + kc*32 + blane));
                        MMA16816(acc[0][0], a00,a01,a02,a03, b0,b1);
                        MMA16816(acc[0][1], a00,a01,a02,a03, b2,b3);
                        MMA16816(acc[1][0], a10,a11,a12,a13, b0,b1);
                        MMA16816(acc[1][1], a10,a11,a12,a13, b2,b3);
                    }
                }
            }
        }

#pragma unroll
        for (int r = 0; r < 2; r++)
#pragma unroll
        for (int s = 0; s < 2; s++) {
            int oc = nh*16 + s*8 + tg*2;
            float b0v = bs[oc], b1v = bs[oc+1];
#pragma unroll
            for (int half = 0; half < 2; half++) {
                int px = mw*16 + g + half*8;
                int gx = x0 + px;
                size_t pix = (size_t)k*HWPIX + (size_t)(y0+r)*WW + gx;
                float v0 = acc[r][s][half*2]   + b0v;
                float v1 = acc[r][s][half*2+1] + b1v;
                union { __nv_bfloat16 b[2]; uint32_t u; } H, L;
                H.b[0] = __float2bfloat16(v0);
                H.b[1] = __float2bfloat16(v1);
                L.b[0] = __float2bfloat16(v0 - __bfloat162float(H.b[0]));
                L.b[1] = __float2bfloat16(v1 - __bfloat162float(H.b[1]));
                *(uint32_t*)(g_ah + pix*64 + 32 + oc) = H.u;
                *(uint32_t*)(g_al + pix*64 + 32 + oc) = L.u;
            }
        }
    }
}

// ======================= un1: 8 -> 32 relu =======================
__global__ void un1_kernel(const float* __restrict__ kw, const float* __restrict__ bw)
{
    __shared__ float wgt[2304];
    int tx = threadIdx.x, ty = threadIdx.y, tid = ty*32 + tx;
    for (int i = tid; i < 2304; i += 256) wgt[i] = kw[i];
    __syncthreads();
    int x = blockIdx.x*32 + tx, y = blockIdx.y*8 + ty;
    float4 acc[8];
#pragma unroll
    for (int j = 0; j < 8; j++) acc[j] = ((const float4*)bw)[j];
    for (int dy = 0; dy < 3; dy++)
    for (int dx = 0; dx < 3; dx++) {
        int iy = y + dy - 1, ix = x + dx - 1;
        if (iy < 0 || iy >= HH || ix < 0 || ix >= WW) continue;
        const float* fp = g_fuse + ((size_t)iy*WW + ix)*8;
        float4 f0 = ((const float4*)fp)[0];
        float4 f1 = ((const float4*)fp)[1];
        float fv[8] = {f0.x,f0.y,f0.z,f0.w,f1.x,f1.y,f1.z,f1.w};
        const float* wr = wgt + (dy*3 + dx)*256;
#pragma unroll
        for (int ic = 0; ic < 8; ic++) {
            float v = fv[ic];
            const float4* w4 = (const float4*)(wr + ic*32);
#pragma unroll
            for (int j = 0; j < 8; j++) {
                float4 w = w4[j];
                acc[j].x=fmaf(v,w.x,acc[j].x); acc[j].y=fmaf(v,w.y,acc[j].y);
                acc[j].z=fmaf(v,w.z,acc[j].z); acc[j].w=fmaf(v,w.w,acc[j].w);
            }
        }
    }
    float* dst = g_u32 + ((size_t)y*WW + x)*32;
#pragma unroll
    for (int j = 0; j < 8; j++) {
        float4 o;
        o.x=fmaxf(acc[j].x,0.f); o.y=fmaxf(acc[j].y,0.f);
        o.z=fmaxf(acc[j].z,0.f); o.w=fmaxf(acc[j].w,0.f);
        ((float4*)dst)[j] = o;
    }
}

// ======================= un2: 32 -> 3 =======================
__global__ void un2_kernel(const float* __restrict__ kw, const float* __restrict__ bw,
                           float* __restrict__ out)
{
    __shared__ float wgt[864];
    int tx = threadIdx.x, ty = threadIdx.y, tid = ty*32 + tx;
    for (int i = tid; i < 864; i += 256) wgt[i] = kw[i];
    __syncthreads();
    int x = blockIdx.x*32 + tx, y = blockIdx.y*8 + ty;
    float a0 = bw[0], a1 = bw[1], a2 = bw[2];
    for (int dy = 0; dy < 3; dy++)
    for (int dx = 0; dx < 3; dx++) {
        int iy = y + dy - 1, ix = x + dx - 1;
        if (iy < 0 || iy >= HH || ix < 0 || ix >= WW) continue;
        const float* up = g_u32 + ((size_t)iy*WW + ix)*32;
        const float* wr = wgt + (dy*3 + dx)*96;
#pragma unroll
        for (int ic4 = 0; ic4 < 8; ic4++) {
            float4 v = ((const float4*)up)[ic4];
            float vv[4] = {v.x, v.y, v.z, v.w};
#pragma unroll
            for (int j = 0; j < 4; j++) {
                int ic = ic4*4 + j;
                a0 = fmaf(vv[j], wr[ic*3 + 0], a0);
                a1 = fmaf(vv[j], wr[ic*3 + 1], a1);
                a2 = fmaf(vv[j], wr[ic*3 + 2], a2);
            }
        }
    }
    float* dst = out + ((size_t)y*WW + x)*3;
    dst[0]=a0; dst[1]=a1; dst[2]=a2;
}

// ======================= launch =======================
extern "C" void kernel_launch(void* const* d_in, const int* in_sizes, int n_in,
                              void* d_out, int out_size)
{
    const float* colors = (const float*)d_in[0];
    const float* ray    = (const float*)d_in[1];
    const float* zbufs  = (const float*)d_in[2];
    const float* W1 = (const float*)d_in[3];  const float* b1 = (const float*)d_in[4];
    const float* W2 = (const float*)d_in[5];  const float* b2 = (const float*)d_in[6];
    const float* W3 = (const float*)d_in[7];  const float* b3 = (const float*)d_in[8];
    const float* W4 = (const float*)d_in[9];  const float* b4 = (const float*)d_in[10];
    const float* k_sup1 = (const float*)d_in[11]; const float* b_sup1 = (const float*)d_in[12];
    const float* k_sup2 = (const float*)d_in[13]; const float* b_sup2 = (const float*)d_in[14];
    const float* k_mpn1 = (const float*)d_in[15]; const float* b_mpn1 = (const float*)d_in[16];
    const float* k_mpn2 = (const float*)d_in[17]; const float* b_mpn2 = (const float*)d_in[18];
    const float* k_un1  = (const float*)d_in[19]; const float* b_un1  = (const float*)d_in[20];
    const float* k_un2  = (const float*)d_in[21]; const float* b_un2  = (const float*)d_in[22];
    float* out = (float*)d_out;

    static cudaStream_t sB = nullptr;
    static cudaEvent_t evRoot = nullptr, evB = nullptr;
    if (sB == nullptr) {
        cudaStreamCreateWithFlags(&sB, cudaStreamNonBlocking);
        cudaEventCreateWithFlags(&evRoot, cudaEventDisableTiming);
        cudaEventCreateWithFlags(&evB, cudaEventDisableTiming);
    }

    cudaFuncSetAttribute(mlp_tc_kernel, cudaFuncAttributeMaxDynamicSharedMemorySize, MLP_TC_SMEM);
    cudaFuncSetAttribute(sup2_tc_kernel, cudaFuncAttributeMaxDynamicSharedMemorySize, SUP2_SMEM);
    cudaFuncSetAttribute(conv64_kernel<0>, cudaFuncAttributeMaxDynamicSharedMemorySize, CONV_SMEM);
    cudaFuncSetAttribute(conv64_kernel<1>, cudaFuncAttributeMaxDynamicSharedMemorySize, CONV_SMEM);

    cudaEventRecord(evRoot, 0);
    cudaStreamWaitEvent(sB, evRoot, 0);

    mlpprep_kernel<<<144, 256>>>(W2, W3, W4);
    mlp_tc_kernel<<<148, 256, MLP_TC_SMEM>>>(ray, zbufs, W1, b1, b2, W3, b3, b4);

    wprep_kernel<<<288, 256, 0, sB>>>(k_mpn1, 0);
    wprep_kernel<<<288, 256, 0, sB>>>(k_mpn2, 1);
    wprep_sup2_kernel<<<144, 256, 0, sB>>>(k_sup2);
    sup1_kernel<<<dim3(16,64,8), dim3(32,8), 0, sB>>>(colors, k_sup1, b_sup1);
    sup2_tc_kernel<<<dim3(256,8), 512, SUP2_SMEM, sB>>>(b_sup2);

    cudaEventRecord(evB, sB);
    cudaStreamWaitEvent(0, evB, 0);

    conv64_kernel<0><<<dim3(256,8), 512, CONV_SMEM>>>(b_mpn1);
    conv64_kernel<1><<<dim3(256,8), 512, CONV_SMEM>>>(b_mpn2);
    un1_kernel<<<dim3(16,64), dim3(32,8)>>>(k_un1, b_un1);
    un2_kernel<<<dim3(16,64), dim3(32,8)>>>(k_un2, b_un2, out);
}

// round 15
// speedup vs baseline: 1.7194x; 1.0502x over previous
#include <cuda_runtime.h>
#include <cuda_bf16.h>
#include <cstdint>
#include <math.h>

#define HH 512
#define WW 512
#define HWPIX (HH*WW)

// ---------------- scratch (device globals) ----------------
__device__ __nv_bfloat16 g_ah[134217728];  // [8][H][W][64] fm hi
__device__ __nv_bfloat16 g_al[134217728];  // fm lo
__device__ __nv_bfloat16 g_bh[134217728];  // sup1 out, later relu(mpn1) hi
__device__ __nv_bfloat16 g_bl[134217728];  // lo
__device__ float g_fuse[2097152];          // [H][W][8]
__device__ __nv_bfloat16 g_w1t[73728];     // conv mpn1 [2][9][64][64]
__device__ __nv_bfloat16 g_w2t[73728];     // conv mpn2
__device__ __nv_bfloat16 g_wst[36864];     // conv sup2 [2][9][32][64] (ic padded)
__device__ __nv_bfloat16 g_w2m[32768];     // mlp W2 [2][128][128] (n,k)
__device__ __nv_bfloat16 g_w3m[32768];     // mlp W3 rows 0..127
__device__ __nv_bfloat16 g_w4m[8192];      // mlp W4 [2][32][128]

#define SWZ(off) ((off) ^ (((off) >> 3) & 0x70))

__device__ __forceinline__ uint32_t smem_u32(const void* p) {
    uint32_t a;
    asm("{ .reg .u64 t; cvta.to.shared.u64 t, %1; cvt.u32.u64 %0, t; }" : "=r"(a) : "l"(p));
    return a;
}
#define LDSM4(r0,r1,r2,r3,addr) \
    asm volatile("ldmatrix.sync.aligned.m8n8.x4.shared.b16 {%0,%1,%2,%3}, [%4];" \
        : "=r"(r0), "=r"(r1), "=r"(r2), "=r"(r3) : "r"(addr))
#define MMA16816(c,a0,a1,a2,a3,b0,b1) \
    asm volatile("mma.sync.aligned.m16n8k16.row.col.f32.bf16.bf16.f32 " \
        "{%0,%1,%2,%3},{%4,%5,%6,%7},{%8,%9},{%0,%1,%2,%3};" \
        : "+f"((c)[0]), "+f"((c)[1]), "+f"((c)[2]), "+f"((c)[3]) \
        : "r"(a0), "r"(a1), "r"(a2), "r"(a3), "r"(b0), "r"(b1))

__device__ __forceinline__ void split_store8(__nv_bfloat16* dh, __nv_bfloat16* dl, const float* v) {
    union { __nv_bfloat16 b[8]; uint4 u; } Hh, Ll;
#pragma unroll
    for (int j = 0; j < 8; j++) {
        __nv_bfloat16 hb = __float2bfloat16(v[j]);
        Hh.b[j] = hb;
        Ll.b[j] = __float2bfloat16(v[j] - __bfloat162float(hb));
    }
    *(uint4*)dh = Hh.u; *(uint4*)dl = Ll.u;
}

// ======================= MLP weight prep (transpose + split) =======================
__global__ void mlpprep_kernel(const float* __restrict__ W2, const float* __restrict__ W3,
                               const float* __restrict__ W4)
{
    int idx = blockIdx.x*256 + threadIdx.x;
    if (idx >= 36864) return;
    if (idx < 16384) {
        int n = idx >> 7, k = idx & 127;
        float w = W2[k*128 + n];
        __nv_bfloat16 hb = __float2bfloat16(w);
        g_w2m[idx] = hb;
        g_w2m[16384 + idx] = __float2bfloat16(w - __bfloat162float(hb));
    } else if (idx < 32768) {
        int j = idx - 16384;
        int n = j >> 7, k = j & 127;
        float w = W3[k*128 + n];
        __nv_bfloat16 hb = __float2bfloat16(w);
        g_w3m[j] = hb;
        g_w3m[16384 + j] = __float2bfloat16(w - __bfloat162float(hb));
    } else {
        int j = idx - 32768;
        int n = j >> 7, k = j & 127;
        float w = W4[k*32 + n];
        __nv_bfloat16 hb = __float2bfloat16(w);
        g_w4m[j] = hb;
        g_w4m[4096 + j] = __float2bfloat16(w - __bfloat162float(hb));
    }
}

// ======================= tensor MLP (256 threads) =======================
#define MW2H 0
#define MW2L 32768
#define MW3H 65536
#define MW3L 98304
#define MW4H 131072
#define MW4L 139264
#define MAH  147456
#define MAL  163840
#define MBH  180224
#define MBL  196608
#define MXS  212992
#define MW3D 215040
#define MB1  216576
#define MB2  217088
#define MB3  217600
#define MB4  218112
#define MW1  218240
#define MLP_TC_SMEM 219776

__device__ __forceinline__ void gemm64(uint32_t sb, int ahOff, int alOff, int whOff, int wlOff,
                                       int mw, int nbase, int npairs, int lane, float (*acc)[4])
{
    const int ar = mw*16 + (lane & 15);
    const uint32_t aRow = sb + ar*256;
    const int arx = ar & 7;
    const int brl = (lane & 7) + ((lane & 16) >> 1);
    const int cbk = (lane & 8) >> 3;
#pragma unroll
    for (int kc = 0; kc < 8; kc++) {
        int ca = kc*2 + (lane >> 4);
        uint32_t aoff = (uint32_t)((ca ^ arx) << 4);
        uint32_t ah0,ah1,ah2,ah3, al0,al1,al2,al3;
        LDSM4(ah0,ah1,ah2,ah3, aRow + ahOff + aoff);
        LDSM4(al0,al1,al2,al3, aRow + alOff + aoff);
#pragma unroll
        for (int ns = 0; ns < npairs; ns++) {
            int br = nbase + ns*16 + brl;
            int cb = kc*2 + cbk;
            uint32_t boff = br*256 + (uint32_t)(((cb ^ (br & 7))) << 4);
            uint32_t b0,b1,b2,b3;
            LDSM4(b0,b1,b2,b3, sb + whOff + boff);
            MMA16816(acc[ns*2],   ah0,ah1,ah2,ah3, b0,b1);
            MMA16816(acc[ns*2+1], ah0,ah1,ah2,ah3, b2,b3);
            MMA16816(acc[ns*2],   al0,al1,al2,al3, b0,b1);
            MMA16816(acc[ns*2+1], al0,al1,al2,al3, b2,b3);
            LDSM4(b0,b1,b2,b3, sb + wlOff + boff);
            MMA16816(acc[ns*2],   ah0,ah1,ah2,ah3, b0,b1);
            MMA16816(acc[ns*2+1], ah0,ah1,ah2,ah3, b2,b3);
        }
    }
}

__device__ __forceinline__ void act_store_pair(char* csm, int hOff, int lOff,
                                               int r, int n, float v0, float v1)
{
    uint32_t off = r*256 + (uint32_t)((((n>>3) ^ (r&7))) << 4) + (n&7)*2;
    union { __nv_bfloat16 b[2]; uint32_t u; } H, L;
    H.b[0] = __float2bfloat16(v0);
    H.b[1] = __float2bfloat16(v1);
    L.b[0] = __float2bfloat16(v0 - __bfloat162float(H.b[0]));
    L.b[1] = __float2bfloat16(v1 - __bfloat162float(H.b[1]));
    *(uint32_t*)(csm + hOff + off) = H.u;
    *(uint32_t*)(csm + lOff + off) = L.u;
}

__global__ void __launch_bounds__(256, 1) mlp_tc_kernel(
    const float* __restrict__ ray, const float* __restrict__ zbufs,
    const float* __restrict__ W1, const float* __restrict__ b1,
    const float* __restrict__ b2, const float* __restrict__ W3,
    const float* __restrict__ b3, const float* __restrict__ b4)
{
    extern __shared__ char csm[];
    const uint32_t sb = smem_u32(csm);
    const int tid = threadIdx.x, lane = tid & 31, wid = tid >> 5;
    const int mw = wid & 3, nh = wid >> 2;

    for (int i = tid; i < 4096; i += 256) {
        int term = i >> 11, j = i & 2047;
        int n = j >> 4, c = j & 15;
        uint32_t doff = n*256 + (uint32_t)((c ^ (n&7)) << 4);
        uint4 v2 = *(const uint4*)(g_w2m + term*16384 + n*128 + c*8);
        *(uint4*)(csm + MW2H + term*32768 + doff) = v2;
        uint4 v3 = *(const uint4*)(g_w3m + term*16384 + n*128 + c*8);
        *(uint4*)(csm + MW3H + term*32768 + doff) = v3;
        if (n < 32) {
            uint4 v4 = *(const uint4*)(g_w4m + term*4096 + n*128 + c*8);
            *(uint4*)(csm + MW4H + term*8192 + doff) = v4;
        }
    }
    for (int i = tid; i < 128; i += 256) {
        ((float*)(csm+MB1))[i] = b1[i];
        ((float*)(csm+MB2))[i] = b2[i];
        ((float*)(csm+MB3))[i] = b3[i];
    }
    if (tid < 32) ((float*)(csm+MB4))[tid] = b4[tid];
    for (int i = tid; i < 384; i += 256) {
        ((float*)(csm+MW1))[i]  = W1[i];
        ((float*)(csm+MW3D))[i] = W3[16384 + i];
    }
    __syncthreads();

    float* xs = (float*)(csm + MXS);
    const float* b2s = (const float*)(csm + MB2);
    const float* b3s = (const float*)(csm + MB3);
    const float* b4s = (const float*)(csm + MB4);

    for (int t = blockIdx.x; t < 32768; t += gridDim.x) {
        if (tid < 64) {
            int p  = t*64 + tid;
            int yx = p & (HWPIX - 1);
            int k  = p >> 18;
            const float* r = ray + (size_t)yx*7;
            float ox=r[0], oy=r[1], oz=r[2], dx=r[3], dy=r[4], dz=r[5], cs=r[6];
            float z = zbufs[(size_t)yx*8 + k];
            float s = z / cs;
            float* x = xs + tid*8;
            x[0]=ox+dx*s; x[1]=oy+dy*s; x[2]=oz+dz*s;
            x[3]=dx; x[4]=dy; x[5]=dz;
            x[6]=(z>0.f)?1.f:0.f; x[7]=0.f;
        }
        __syncthreads();

        {
            int p = tid & 63, ug = tid >> 6;
            const float* xp = xs + p*8;
            float x0=xp[0], x1=xp[1], x2=xp[2];
            const float* w1s = (const float*)(csm + MW1);
            const float* b1s = (const float*)(csm + MB1);
            float v[8];
#pragma unroll
            for (int q = 0; q < 4; q++) {
#pragma unroll
                for (int j = 0; j < 8; j++) {
                    int u = ug*32 + q*8 + j;
                    v[j] = fmaxf(b1s[u] + x0*w1s[u] + x1*w1s[128+u] + x2*w1s[256+u], 0.f);
                }
                int c = ug*4 + q;
                uint32_t off = p*256 + (uint32_t)((c ^ (p&7)) << 4);
                split_store8((__nv_bfloat16*)(csm + MAH + off),
                             (__nv_bfloat16*)(csm + MAL + off), v);
            }
        }
        __syncthreads();

        {
            float acc[8][4] = {};
            gemm64(sb, MAH, MAL, MW2H, MW2L, mw, nh*64, 4, lane, acc);
            int r0 = mw*16 + (lane>>2);
#pragma unroll
            for (int ns = 0; ns < 8; ns++) {
                int n = nh*64 + ns*8 + (lane&3)*2;
                float bb0 = b2s[n], bb1 = b2s[n+1];
                act_store_pair(csm, MBH, MBL, r0,   n, fmaxf(acc[ns][0]+bb0,0.f), fmaxf(acc[ns][1]+bb1,0.f));
                act_store_pair(csm, MBH, MBL, r0+8, n, fmaxf(acc[ns][2]+bb0,0.f), fmaxf(acc[ns][3]+bb1,0.f));
            }
        }
        __syncthreads();

        {
            float acc[8][4] = {};
            gemm64(sb, MBH, MBL, MW3H, MW3L, mw, nh*64, 4, lane, acc);
            int r0 = mw*16 + (lane>>2);
            const float* w3d = (const float*)(csm + MW3D);
            float dx0 = xs[r0*8+3],     dy0 = xs[r0*8+4],     dz0 = xs[r0*8+5];
            float dx1 = xs[(r0+8)*8+3], dy1 = xs[(r0+8)*8+4], dz1 = xs[(r0+8)*8+5];
#pragma unroll
            for (int ns = 0; ns < 8; ns++) {
                int n = nh*64 + ns*8 + (lane&3)*2;
                float w0a=w3d[n],   w0b=w3d[128+n],   w0c=w3d[256+n];
                float w1a=w3d[n+1], w1b=w3d[128+n+1], w1c=w3d[256+n+1];
                float v0 = fmaxf(acc[ns][0] + b3s[n]   + dx0*w0a + dy0*w0b + dz0*w0c, 0.f);
                float v1 = fmaxf(acc[ns][1] + b3s[n+1] + dx0*w1a + dy0*w1b + dz0*w1c, 0.f);
                float v2 = fmaxf(acc[ns][2] + b3s[n]   + dx1*w0a + dy1*w0b + dz1*w0c, 0.f);
                float v3 = fmaxf(acc[ns][3] + b3s[n+1] + dx1*w1a + dy1*w1b + dz1*w1c, 0.f);
                act_store_pair(csm, MAH, MAL, r0,   n, v0, v1);
                act_store_pair(csm, MAH, MAL, r0+8, n, v2, v3);
            }
        }
        __syncthreads();

        {
            float acc[2][4] = {};
            gemm64(sb, MAH, MAL, MW4H, MW4L, mw, nh*16, 1, lane, acc);
            int r0 = mw*16 + (lane>>2);
#pragma unroll
            for (int ns = 0; ns < 2; ns++) {
                int n = nh*16 + ns*8 + (lane&3)*2;
                float bb0 = b4s[n], bb1 = b4s[n+1];
#pragma unroll
                for (int hh = 0; hh < 2; hh++) {
                    int r = r0 + hh*8;
                    float mk = xs[r*8+6];
                    size_t P = (size_t)t*64 + r;
                    float v0 = (acc[ns][hh*2]   + bb0)*mk;
                    float v1 = (acc[ns][hh*2+1] + bb1)*mk;
                    union { __nv_bfloat16 b[2]; uint32_t u; } H, L;
                    H.b[0] = __float2bfloat16(v0);
                    H.b[1] = __float2bfloat16(v1);
                    L.b[0] = __float2bfloat16(v0 - __bfloat162float(H.b[0]));
                    L.b[1] = __float2bfloat16(v1 - __bfloat162float(H.b[1]));
                    *(uint32_t*)(g_ah + P*64 + n) = H.u;
                    *(uint32_t*)(g_al + P*64 + n) = L.u;
                }
            }
        }
        __syncthreads();
    }
}

// ======================= sup1: 3 -> 32 relu, split-store (ch 0..31 only) ========
__global__ void sup1_kernel(const float* __restrict__ colors,
                            const float* __restrict__ kw, const float* __restrict__ bw)
{
    __shared__ float wgt[864];
    int tx = threadIdx.x, ty = threadIdx.y, tid = ty*32 + tx;
    for (int i = tid; i < 864; i += 256) wgt[i] = kw[i];
    __syncthreads();
    int x = blockIdx.x*32 + tx, y = blockIdx.y*8 + ty, k = blockIdx.z;
    float4 acc[8];
#pragma unroll
    for (int j = 0; j < 8; j++) acc[j] = ((const float4*)bw)[j];
    for (int dy = 0; dy < 3; dy++)
    for (int dx = 0; dx < 3; dx++) {
        int iy = y + dy - 1, ix = x + dx - 1;
        if (iy < 0 || iy >= HH || ix < 0 || ix >= WW) continue;
        const float* cp = colors + ((size_t)iy*WW + ix)*24 + k*3;
        const float* wr = wgt + (dy*3 + dx)*96;
#pragma unroll
        for (int ic = 0; ic < 3; ic++) {
            float v = cp[ic];
            const float4* w4 = (const float4*)(wr + ic*32);
#pragma unroll
            for (int j = 0; j < 8; j++) {
                float4 w = w4[j];
                acc[j].x=fmaf(v,w.x,acc[j].x); acc[j].y=fmaf(v,w.y,acc[j].y);
                acc[j].z=fmaf(v,w.z,acc[j].z); acc[j].w=fmaf(v,w.w,acc[j].w);
            }
        }
    }
    size_t pix = (size_t)k*HWPIX + (size_t)y*WW + x;
    float v[32];
#pragma unroll
    for (int j = 0; j < 8; j++) {
        v[j*4]  =fmaxf(acc[j].x,0.f); v[j*4+1]=fmaxf(acc[j].y,0.f);
        v[j*4+2]=fmaxf(acc[j].z,0.f); v[j*4+3]=fmaxf(acc[j].w,0.f);
    }
#pragma unroll
    for (int q = 0; q < 4; q++)
        split_store8(g_bh + pix*64 + q*8, g_bl + pix*64 + q*8, v + q*8);
}

// ======================= conv weight preps =======================
__global__ void wprep_kernel(const float* __restrict__ kw, int which)
{
    int idx = blockIdx.x*256 + threadIdx.x;
    if (idx >= 73728) return;
    int t = idx / 36864, r = idx % 36864;
    int p = r >> 12, q = r & 4095;
    int oc = q >> 6, ic = q & 63;
    float w = kw[((size_t)p*64 + ic)*64 + oc];
    __nv_bfloat16 hb = __float2bfloat16(w);
    __nv_bfloat16 o = t ? __float2bfloat16(w - __bfloat162float(hb)) : hb;
    (which ? g_w2t : g_w1t)[idx] = o;
}

__global__ void wprep_sup2_kernel(const float* __restrict__ kw)
{
    int idx = blockIdx.x*256 + threadIdx.x;
    if (idx >= 36864) return;
    int t = idx / 18432, r = idx % 18432;
    int tap = r >> 11, q = r & 2047;
    int oc = q >> 6, ic = q & 63;
    float w = (ic < 32) ? kw[((size_t)tap*32 + ic)*32 + oc] : 0.f;
    __nv_bfloat16 hb = __float2bfloat16(w);
    g_wst[idx] = t ? __float2bfloat16(w - __bfloat162float(hb)) : hb;
}

// ===== mma.sync 64->64 3x3 conv, 2 output rows/block, 512 threads, prefetch staging =====
#define PITCH 136
#define WOFF  69632
#define BOFF (WOFF + 147456)
#define CONV_SMEM (BOFF + 256)

template<int MODE>
__global__ void __launch_bounds__(512, 1) conv64_kernel(const float* __restrict__ bias)
{
    extern __shared__ char csm[];
    const uint32_t sb = smem_u32(csm);
    const int tid = threadIdx.x, wid = tid >> 5, lane = tid & 31;
    const int mw = wid & 7, nh = wid >> 3;
    const int y0 = blockIdx.x*2, k = blockIdx.y;
    const int g = lane >> 2, tg = lane & 3;

    {
        const __nv_bfloat16* ws = MODE ? g_w2t : g_w1t;
        for (int i = tid; i < 9216; i += 512) {
            uint4 v = *(const uint4*)(ws + i*8);
            *(uint4*)(csm + WOFF + SWZ(i*16)) = v;
        }
    }
    if (tid < 64) ((float*)(csm + BOFF))[tid] = bias[tid];

    const __nv_bfloat16* srcH = MODE ? g_bh : g_ah;
    const __nv_bfloat16* srcL = MODE ? g_bl : g_al;
    float* bs = (float*)(csm + BOFF);

    const uint32_t alane = (mw*16 + (lane & 15))*128 + (lane >> 4)*16;
    const uint32_t blane = ((lane & 7) + ((lane & 16) >> 1))*128 + (lane & 8)*2;

    for (int t = 0; t < 4; t++) {
        const int x0 = t*128;
        float acc[2][4][4];
#pragma unroll
        for (int r = 0; r < 2; r++)
#pragma unroll
            for (int s = 0; s < 4; s++)
#pragma unroll
                for (int j = 0; j < 4; j++) acc[r][s][j] = 0.f;

        for (int pass = 0; pass < 2; pass++) {
            const __nv_bfloat16* src = pass ? srcL : srcH;
            // prefetch window into registers BEFORE sync (hides DRAM latency behind prior MMA)
            uint4 gv[9];
#pragma unroll
            for (int it = 0; it < 9; it++) {
                int idx = tid + it*512;
                gv[it] = make_uint4(0,0,0,0);
                if (idx < 4160) {
                    int r = idx >> 3, c = idx & 7;
                    int dyw = r/130, sx = r - dyw*130;
                    int iy = y0 - 1 + dyw, ix = x0 + sx - 1;
                    if (iy >= 0 && iy < HH && (unsigned)ix < WW)
                        gv[it] = *(const uint4*)(src + ((size_t)k*HWPIX + (size_t)iy*WW + ix)*64 + c*8);
                }
            }
            __syncthreads();
#pragma unroll
            for (int it = 0; it < 9; it++) {
                int idx = tid + it*512;
                if (idx < 4160) {
                    int r = idx >> 3, c = idx & 7;
                    int dyw = r/130, sx = r - dyw*130;
                    *(uint4*)(csm + SWZ((dyw*PITCH + sx)*128 + c*16)) = gv[it];
                }
            }
            __syncthreads();

            const int nterm = pass ? 1 : 2;
            for (int tap = 0; tap < 9; tap++) {
                int dy = tap/3, dxo = tap - dy*3;
#pragma unroll
                for (int kc = 0; kc < 4; kc++) {
                    uint32_t a00,a01,a02,a03, a10,a11,a12,a13;
                    LDSM4(a00,a01,a02,a03, sb + SWZ((dy*PITCH + dxo)*128 + alane + kc*32));
                    LDSM4(a10,a11,a12,a13, sb + SWZ(((dy+1)*PITCH + dxo)*128 + alane + kc*32));
                    for (int tm = 0; tm < nterm; tm++) {
                        uint32_t wb = sb + WOFF + tm*73728;
#pragma unroll
                        for (int ns = 0; ns < 2; ns++) {
                            uint32_t b0,b1,b2,b3;
                            LDSM4(b0,b1,b2,b3, wb + SWZ(tap*8192 + (nh*2+ns)*2048 + kc*32 + blane));
                            MMA16816(acc[0][ns*2],   a00,a01,a02,a03, b0,b1);
                            MMA16816(acc[0][ns*2+1], a00,a01,a02,a03, b2,b3);
                            MMA16816(acc[1][ns*2],   a10,a11,a12,a13, b0,b1);
                            MMA16816(acc[1][ns*2+1], a10,a11,a12,a13, b2,b3);
                        }
                    }
                }
            }
        }

        if (MODE == 0) {
#pragma unroll
            for (int r = 0; r < 2; r++)
#pragma unroll
            for (int s = 0; s < 4; s++) {
                int oc = nh*32 + s*8 + tg*2;
                float b0v = bs[oc], b1v = bs[oc+1];
#pragma unroll
                for (int half = 0; half < 2; half++) {
                    int px = mw*16 + g + half*8;
                    int gx = x0 + px;
                    size_t pix = (size_t)k*HWPIX + (size_t)(y0+r)*WW + gx;
                    float v0 = fmaxf(acc[r][s][half*2]   + b0v, 0.f);
                    float v1 = fmaxf(acc[r][s][half*2+1] + b1v, 0.f);
                    union { __nv_bfloat16 b[2]; uint32_t u; } H, L;
                    H.b[0] = __float2bfloat16(v0);
                    H.b[1] = __float2bfloat16(v1);
                    L.b[0] = __float2bfloat16(v0 - __bfloat162float(H.b[0]));
                    L.b[1] = __float2bfloat16(v1 - __bfloat162float(H.b[1]));
                    *(uint32_t*)(g_bh + pix*64 + oc) = H.u;
                    *(uint32_t*)(g_bl + pix*64 + oc) = L.u;
                }
            }
        } else {
            float* fsm = (float*)csm;
            for (int r = 0; r < 2; r++) {
                __syncthreads();
#pragma unroll
                for (int s = 0; s < 4; s++) {
                    int oc = nh*32 + s*8 + tg*2;
#pragma unroll
                    for (int half = 0; half < 2; half++) {
                        int px = mw*16 + g + half*8;
                        fsm[px*68 + oc]     = acc[r][s][half*2]   + bs[oc];
                        fsm[px*68 + oc + 1] = acc[r][s][half*2+1] + bs[oc+1];
                    }
                }
                __syncthreads();
                if (tid < 128) {
                    int gx = x0 + tid;
                    size_t pix = (size_t)k*HWPIX + (size_t)(y0+r)*WW + gx;
                    const uint4* ah4 = (const uint4*)(g_ah + pix*64);
                    const uint4* al4 = (const uint4*)(g_al + pix*64);
                    float alpha = 1.f, fuse = 0.f;
#pragma unroll
                    for (int q = 0; q < 8; q++) {
                        union { uint4 u; __nv_bfloat16 b[8]; } Ha, La;
                        Ha.u = ah4[q]; La.u = al4[q];
#pragma unroll
                        for (int j = 0; j < 8; j++) {
                            float a = fsm[tid*68 + q*8 + j];
                            float m = 1.f/(1.f + expf(-a));
                            float f = __bfloat162float(Ha.b[j]) + __bfloat162float(La.b[j]);
                            fuse += f*m*alpha;
                            alpha *= (1.f - m);
                        }
                    }
                    g_fuse[((size_t)(y0+r)*WW + gx)*8 + k] = fuse;
                }
            }
        }
    }
}

// ===== sup2 tensor conv, 2 rows/block, 512 threads, prefetch staging =====
#define W2OFF 69632
#define B2OFF (W2OFF + 73728)
#define SUP2_SMEM (B2OFF + 128)

__global__ void __launch_bounds__(512, 1) sup2_tc_kernel(const float* __restrict__ bias)
{
    extern __shared__ char csm[];
    const uint32_t sb = smem_u32(csm);
    const int tid = threadIdx.x, wid = tid >> 5, lane = tid & 31;
    const int mw = wid & 7, nh = wid >> 3;
    const int y0 = blockIdx.x*2, k = blockIdx.y;
    const int g = lane >> 2, tg = lane & 3;

    for (int i = tid; i < 4608; i += 512) {
        uint4 v = *(const uint4*)(g_wst + i*8);
        *(uint4*)(csm + W2OFF + SWZ(i*16)) = v;
    }
    if (tid < 32) ((float*)(csm + B2OFF))[tid] = bias[tid];
    float* bs = (float*)(csm + B2OFF);

    const uint32_t alane = (mw*16 + (lane & 15))*128 + (lane >> 4)*16;
    const uint32_t blane = ((lane & 7) + ((lane & 16) >> 1))*128 + (lane & 8)*2;

    for (int t = 0; t < 4; t++) {
        const int x0 = t*128;
        float acc[2][2][4];
#pragma unroll
        for (int r = 0; r < 2; r++)
#pragma unroll
            for (int s = 0; s < 2; s++)
#pragma unroll
                for (int j = 0; j < 4; j++) acc[r][s][j] = 0.f;

        for (int pass = 0; pass < 2; pass++) {
            const __nv_bfloat16* src = pass ? g_bl : g_bh;
            uint4 gv[5];
#pragma unroll
            for (int it = 0; it < 5; it++) {
                int idx = tid + it*512;
                gv[it] = make_uint4(0,0,0,0);
                if (idx < 2080) {
                    int r = idx >> 2, c = idx & 3;
                    int dyw = r/130, sx = r - dyw*130;
                    int iy = y0 - 1 + dyw, ix = x0 + sx - 1;
                    if (iy >= 0 && iy < HH && (unsigned)ix < WW)
                        gv[it] = *(const uint4*)(src + ((size_t)k*HWPIX + (size_t)iy*WW + ix)*64 + c*8);
                }
            }
            __syncthreads();
#pragma unroll
            for (int it = 0; it < 5; it++) {
                int idx = tid + it*512;
                if (idx < 2080) {
                    int r = idx >> 2, c = idx & 3;
                    int dyw = r/130, sx = r - dyw*130;
                    *(uint4*)(csm + SWZ((dyw*PITCH + sx)*128 + c*16)) = gv[it];
                }
            }
            __syncthreads();

            const int nterm = pass ? 1 : 2;
            for (int tap = 0; tap < 9; tap++) {
                int dy = tap/3, dxo = tap - dy*3;
#pragma unroll
                for (int kc = 0; kc < 2; kc++) {
                    uint32_t a00,a01,a02,a03, a10,a11,a12,a13;
                    LDSM4(a00,a01,a02,a03, sb + SWZ((dy*PITCH + dxo)*128 + alane + kc*32));
                    LDSM4(a10,a11,a12,a13, sb + SWZ(((dy+1)*PITCH + dxo)*128 + alane + kc*32));
                    for (int tm = 0; tm < nterm; tm++) {
                        uint32_t wb = sb + W2OFF + tm*36864;
                        uint32_t b0,b1,b2,b3;
                        LDSM4(b0,b1,b2,b3, wb + SWZ(tap*4096 + nh*2048 + kc*32 + blane));
                        MMA16816(acc[0][0], a00,a01,a02,a03, b0,b1);
                        MMA16816(acc[0][1], a00,a01,a02,a03, b2,b3);
                        MMA16816(acc[1][0], a10,a11,a12,a13, b0,b1);
                        MMA16816(acc[1][1], a10,a11,a12,a13, b2,b3);
                    }
                }
            }
        }

#pragma unroll
        for (int r = 0; r < 2; r++)
#pragma unroll
        for (int s = 0; s < 2; s++) {
            int oc = nh*16 + s*8 + tg*2;
            float b0v = bs[oc], b1v = bs[oc+1];
#pragma unroll
            for (int half = 0; half < 2; half++) {
                int px = mw*16 + g + half*8;
                int gx = x0 + px;
                size_t pix = (size_t)k*HWPIX + (size_t)(y0+r)*WW + gx;
                float v0 = acc[r][s][half*2]   + b0v;
                float v1 = acc[r][s][half*2+1] + b1v;
                union { __nv_bfloat16 b[2]; uint32_t u; } H, L;
                H.b[0] = __float2bfloat16(v0);
                H.b[1] = __float2bfloat16(v1);
                L.b[0] = __float2bfloat16(v0 - __bfloat162float(H.b[0]));
                L.b[1] = __float2bfloat16(v1 - __bfloat162float(H.b[1]));
                *(uint32_t*)(g_ah + pix*64 + 32 + oc) = H.u;
                *(uint32_t*)(g_al + pix*64 + 32 + oc) = L.u;
            }
        }
    }
}

// ======================= fused un1+un2: 8 -> 32 relu -> 3 =======================
#define UN_U1 0
#define UN_W1 44880                  // 340*33*4 = 44880
#define UN_W2 (UN_W1 + 9216)         // 54096
#define UN_SMEM (UN_W2 + 3456 + 32)  // 57584

__global__ void __launch_bounds__(256, 1) un_fused_kernel(
    const float* __restrict__ kw1, const float* __restrict__ bw1,
    const float* __restrict__ kw2, const float* __restrict__ bw2,
    float* __restrict__ out)
{
    extern __shared__ char csm[];
    float* u1   = (float*)(csm + UN_U1);
    float* wgt1 = (float*)(csm + UN_W1);
    float* wgt2 = (float*)(csm + UN_W2);
    const int tid = threadIdx.x;
    const int bx = blockIdx.x, by = blockIdx.y;

    for (int i = tid; i < 2304; i += 256) wgt1[i] = kw1[i];
    for (int i = tid; i < 864; i += 256) wgt2[i] = kw2[i];
    __syncthreads();

    for (int idx = tid; idx < 340; idx += 256) {
        int hx = idx % 34 - 1, hy = idx / 34 - 1;
        int x = bx*32 + hx, y = by*8 + hy;
        float acc[32];
        if ((unsigned)x < WW && (unsigned)y < HH) {
#pragma unroll
            for (int j = 0; j < 32; j++) acc[j] = bw1[j];
            for (int dy = 0; dy < 3; dy++)
            for (int dx = 0; dx < 3; dx++) {
                int iy = y + dy - 1, ix = x + dx - 1;
                if (iy < 0 || iy >= HH || ix < 0 || ix >= WW) continue;
                const float* fp = g_fuse + ((size_t)iy*WW + ix)*8;
                const float* wr = wgt1 + (dy*3 + dx)*256;
#pragma unroll
                for (int ic = 0; ic < 8; ic++) {
                    float v = fp[ic];
                    const float* w = wr + ic*32;
#pragma unroll
                    for (int j = 0; j < 32; j++) acc[j] = fmaf(v, w[j], acc[j]);
                }
            }
#pragma unroll
            for (int j = 0; j < 32; j++) u1[idx*33 + j] = fmaxf(acc[j], 0.f);
        } else {
#pragma unroll
            for (int j = 0; j < 32; j++) u1[idx*33 + j] = 0.f;
        }
    }
    __syncthreads();

    {
        int lx = tid & 31, ly = tid >> 5;
        float a0 = bw2[0], a1 = bw2[1], a2 = bw2[2];
        for (int dy = 0; dy < 3; dy++)
        for (int dx = 0; dx < 3; dx++) {
            const float* up = u1 + ((ly + dy)*34 + (lx + dx))*33;
            const float* wr = wgt2 + (dy*3 + dx)*96;
#pragma unroll
            for (int ic = 0; ic < 32; ic++) {
                float v = up[ic];
                a0 = fmaf(v, wr[ic*3 + 0], a0);
                a1 = fmaf(v, wr[ic*3 + 1], a1);
                a2 = fmaf(v, wr[ic*3 + 2], a2);
            }
        }
        int gx = bx*32 + lx, gy = by*8 + ly;
        float* dst = out + ((size_t)gy*WW + gx)*3;
        dst[0]=a0; dst[1]=a1; dst[2]=a2;
    }
}

// ======================= launch =======================
extern "C" void kernel_launch(void* const* d_in, const int* in_sizes, int n_in,
                              void* d_out, int out_size)
{
    const float* colors = (const float*)d_in[0];
    const float* ray    = (const float*)d_in[1];
    const float* zbufs  = (const float*)d_in[2];
    const float* W1 = (const float*)d_in[3];  const float* b1 = (const float*)d_in[4];
    const float* W2 = (const float*)d_in[5];  const float* b2 = (const float*)d_in[6];
    const float* W3 = (const float*)d_in[7];  const float* b3 = (const float*)d_in[8];
    const float* W4 = (const float*)d_in[9];  const float* b4 = (const float*)d_in[10];
    const float* k_sup1 = (const float*)d_in[11]; const float* b_sup1 = (const float*)d_in[12];
    const float* k_sup2 = (const float*)d_in[13]; const float* b_sup2 = (const float*)d_in[14];
    const float* k_mpn1 = (const float*)d_in[15]; const float* b_mpn1 = (const float*)d_in[16];
    const float* k_mpn2 = (const float*)d_in[17]; const float* b_mpn2 = (const float*)d_in[18];
    const float* k_un1  = (const float*)d_in[19]; const float* b_un1  = (const float*)d_in[20];
    const float* k_un2  = (const float*)d_in[21]; const float* b_un2  = (const float*)d_in[22];
    float* out = (float*)d_out;

    static cudaStream_t sB = nullptr;
    static cudaEvent_t evRoot = nullptr, evB = nullptr;
    if (sB == nullptr) {
        cudaStreamCreateWithFlags(&sB, cudaStreamNonBlocking);
        cudaEventCreateWithFlags(&evRoot, cudaEventDisableTiming);
        cudaEventCreateWithFlags(&evB, cudaEventDisableTiming);
    }

    cudaFuncSetAttribute(mlp_tc_kernel, cudaFuncAttributeMaxDynamicSharedMemorySize, MLP_TC_SMEM);
    cudaFuncSetAttribute(sup2_tc_kernel, cudaFuncAttributeMaxDynamicSharedMemorySize, SUP2_SMEM);
    cudaFuncSetAttribute(conv64_kernel<0>, cudaFuncAttributeMaxDynamicSharedMemorySize, CONV_SMEM);
    cudaFuncSetAttribute(conv64_kernel<1>, cudaFuncAttributeMaxDynamicSharedMemorySize, CONV_SMEM);
    cudaFuncSetAttribute(un_fused_kernel, cudaFuncAttributeMaxDynamicSharedMemorySize, UN_SMEM);

    cudaEventRecord(evRoot, 0);
    cudaStreamWaitEvent(sB, evRoot, 0);

    mlpprep_kernel<<<144, 256>>>(W2, W3, W4);
    mlp_tc_kernel<<<148, 256, MLP_TC_SMEM>>>(ray, zbufs, W1, b1, b2, W3, b3, b4);

    wprep_kernel<<<288, 256, 0, sB>>>(k_mpn1, 0);
    wprep_kernel<<<288, 256, 0, sB>>>(k_mpn2, 1);
    wprep_sup2_kernel<<<144, 256, 0, sB>>>(k_sup2);
    sup1_kernel<<<dim3(16,64,8), dim3(32,8), 0, sB>>>(colors, k_sup1, b_sup1);
    sup2_tc_kernel<<<dim3(256,8), 512, SUP2_SMEM, sB>>>(b_sup2);

    cudaEventRecord(evB, sB);
    cudaStreamWaitEvent(0, evB, 0);

    conv64_kernel<0><<<dim3(256,8), 512, CONV_SMEM>>>(b_mpn1);
    conv64_kernel<1><<<dim3(256,8), 512, CONV_SMEM>>>(b_mpn2);
    un_fused_kernel<<<dim3(16,64), 256, UN_SMEM>>>(k_un1, b_un1, k_un2, b_un2, out);
}